// round 2
// baseline (speedup 1.0000x reference)
#include <cuda_runtime.h>
#include <cstdint>

#define B_ 256
#define T_ 256
#define F_ 512
#define H_ 1024
#define A_ 1000

// ---------------- scratch (static device globals; no allocation) -------------
__device__ float g_xw[(size_t)B_ * T_ * H_];   // 256 MB: input projection
__device__ float g_h[2][B_ * H_];              // ping-pong hidden state
__device__ float g_hid[B_ * H_];
__device__ float g_logits[B_ * A_];
__device__ int   g_action[B_];
__device__ float g_rowloss[B_];

// ---------------- packed fp32x2 FMA helpers (Blackwell) ----------------------
__device__ __forceinline__ unsigned long long pack2(float lo, float hi) {
    unsigned long long r;
    asm("mov.b64 %0, {%1, %2};" : "=l"(r) : "f"(lo), "f"(hi));
    return r;
}
__device__ __forceinline__ void unpack2(unsigned long long v, float& lo, float& hi) {
    asm("mov.b64 {%0, %1}, %2;" : "=f"(lo), "=f"(hi) : "l"(v));
}
__device__ __forceinline__ void ffma2(unsigned long long& d, unsigned long long a,
                                      unsigned long long b) {
    asm("fma.rn.f32x2 %0, %1, %2, %0;" : "+l"(d) : "l"(a), "l"(b));
}

// ---------------- double-buffered SGEMM template -----------------------------
// C[M,N] = act( A[M,K] @ B[K,N] + D[m,n]? + bias[n]? ),  row-major everywhere.
// M % BM == 0, K % BK == 0 required; N may be ragged (guarded per float4).
template <int BM, int BN, int BK, int TM, int TN, int THREADS, bool RELU>
__global__ void __launch_bounds__(THREADS)
sgemm_kernel(int M, int N, int K,
             const float* __restrict__ A, int lda,
             const float* __restrict__ Bm, int ldb,
             const float* __restrict__ D, long ldd,
             const float* __restrict__ bias,
             float* __restrict__ C, int ldc)
{
    static_assert(TN % 4 == 0 && TM % 4 == 0, "");
    constexpr int TX = BN / TN;
    constexpr int TY = BM / TM;
    static_assert(TX * TY == THREADS, "");

    __shared__ float As[2][BK][BM];
    __shared__ float Bs[2][BK][BN];

    const int tid = threadIdx.x;
    const int tx  = tid % TX;
    const int ty  = tid / TX;
    const int bm  = blockIdx.y * BM;
    const int bn  = blockIdx.x * BN;

    constexpr int A_VECS = BM * BK / 4;
    constexpr int A_PER  = A_VECS / THREADS;
    constexpr int B_VECS = BK * BN / 4;
    constexpr int B_PER  = B_VECS / THREADS;
    static_assert(A_VECS % THREADS == 0 && B_VECS % THREADS == 0, "");

    float4 aReg[A_PER];
    float4 bReg[B_PER];

    auto loadA = [&](int k0) {
#pragma unroll
        for (int i = 0; i < A_PER; ++i) {
            int v   = tid + i * THREADS;
            int row = v / (BK / 4);
            int kc  = (v % (BK / 4)) * 4;
            aReg[i] = *reinterpret_cast<const float4*>(
                &A[(long)(bm + row) * lda + k0 + kc]);
        }
    };
    auto loadB = [&](int k0) {
#pragma unroll
        for (int i = 0; i < B_PER; ++i) {
            int v    = tid + i * THREADS;
            int krow = v / (BN / 4);
            int nc   = (v % (BN / 4)) * 4;
            int col  = bn + nc;
            if (col < N)
                bReg[i] = *reinterpret_cast<const float4*>(
                    &Bm[(long)(k0 + krow) * ldb + col]);
            else
                bReg[i] = make_float4(0.f, 0.f, 0.f, 0.f);
        }
    };
    auto storeA = [&](int buf) {
#pragma unroll
        for (int i = 0; i < A_PER; ++i) {
            int v   = tid + i * THREADS;
            int row = v / (BK / 4);
            int kc  = (v % (BK / 4)) * 4;
            As[buf][kc + 0][row] = aReg[i].x;
            As[buf][kc + 1][row] = aReg[i].y;
            As[buf][kc + 2][row] = aReg[i].z;
            As[buf][kc + 3][row] = aReg[i].w;
        }
    };
    auto storeB = [&](int buf) {
#pragma unroll
        for (int i = 0; i < B_PER; ++i) {
            int v    = tid + i * THREADS;
            int krow = v / (BN / 4);
            int nc   = (v % (BN / 4)) * 4;
            *reinterpret_cast<float4*>(&Bs[buf][krow][nc]) = bReg[i];
        }
    };

    unsigned long long acc[TM][TN / 2];
#pragma unroll
    for (int i = 0; i < TM; ++i)
#pragma unroll
        for (int j = 0; j < TN / 2; ++j) acc[i][j] = 0ull;

    loadA(0); loadB(0);
    storeA(0); storeB(0);
    __syncthreads();

    const int nTiles = K / BK;
    for (int kt = 0; kt < nTiles; ++kt) {
        const int cur = kt & 1, nxt = cur ^ 1;
        if (kt + 1 < nTiles) { loadA((kt + 1) * BK); loadB((kt + 1) * BK); }

#pragma unroll
        for (int kk = 0; kk < BK; ++kk) {
            float af[TM];
#pragma unroll
            for (int i = 0; i < TM; i += 4) {
                float4 t = *reinterpret_cast<const float4*>(&As[cur][kk][ty * TM + i]);
                af[i] = t.x; af[i + 1] = t.y; af[i + 2] = t.z; af[i + 3] = t.w;
            }
            unsigned long long b2[TN / 2];
#pragma unroll
            for (int j = 0; j < TN / 4; ++j) {
                ulonglong2 bv = *reinterpret_cast<const ulonglong2*>(
                    &Bs[cur][kk][tx * TN + 4 * j]);
                b2[2 * j] = bv.x; b2[2 * j + 1] = bv.y;
            }
#pragma unroll
            for (int i = 0; i < TM; ++i) {
                unsigned long long a2 = pack2(af[i], af[i]);
#pragma unroll
                for (int j = 0; j < TN / 2; ++j) ffma2(acc[i][j], a2, b2[j]);
            }
        }

        if (kt + 1 < nTiles) { storeA(nxt); storeB(nxt); }
        __syncthreads();
    }

    // epilogue
#pragma unroll
    for (int i = 0; i < TM; ++i) {
        const int m = bm + ty * TM + i;
#pragma unroll
        for (int j = 0; j < TN / 2; ++j) {
            float lo, hi;
            unpack2(acc[i][j], lo, hi);
            float v[2] = {lo, hi};
            const int n0 = bn + tx * TN + 2 * j;
#pragma unroll
            for (int e = 0; e < 2; ++e) {
                const int n = n0 + e;
                if (n < N) {
                    float c = v[e];
                    if (D)    c += D[(long)m * ldd + n];
                    if (bias) c += bias[n];
                    if (RELU) c = fmaxf(c, 0.0f);
                    C[(long)m * ldc + n] = c;
                }
            }
        }
    }
}

// ---------------- threefry2x32 / JAX gumbel ----------------------------------
// Partitionable path (JAX >= 0.4.36 default): bits(i) = o1 ^ o2 where
// (o1,o2) = threefry2x32(key=(0,42), counts=(hi(i)=0, lo(i)=i)).
__device__ __forceinline__ float gumbel_at(uint32_t idx) {
    const uint32_t k0 = 0u, k1 = 42u;
    const uint32_t ks2 = k0 ^ k1 ^ 0x1BD11BDAu;
    uint32_t x0 = k0;          // counts_hi (0) + k0
    uint32_t x1 = idx + k1;    // counts_lo (i) + k1
#define RND(r) { x0 += x1; x1 = ((x1 << (r)) | (x1 >> (32 - (r)))) ^ x0; }
    RND(13) RND(15) RND(26) RND(6)   x0 += k1;  x1 += ks2 + 1u;
    RND(17) RND(29) RND(16) RND(24)  x0 += ks2; x1 += k0 + 2u;
    RND(13) RND(15) RND(26) RND(6)   x0 += k0;  x1 += k1 + 3u;
    RND(17) RND(29) RND(16) RND(24)  x0 += k1;  x1 += ks2 + 4u;
    RND(13) RND(15) RND(26) RND(6)   x0 += ks2; x1 += k0 + 5u;
#undef RND
    const uint32_t bits = x0 ^ x1;
    float f = __uint_as_float((bits >> 9) | 0x3f800000u) - 1.0f;
    float u = fmaxf(f, 1.17549435e-38f);   // == floats*(1-tiny)+tiny; max(tiny, .)
    return -logf(-logf(u));
}

// ---------------- init, softmax+sample, finalize -----------------------------
__global__ void zero_h0_kernel() {
    int i = blockIdx.x * 256 + threadIdx.x;
    if (i < B_ * H_) g_h[0][i] = 0.0f;
}

__global__ void sample_kernel() {
    const int b = blockIdx.x;
    const float* __restrict__ row = g_logits + (long)b * A_;
    const int tid = threadIdx.x;
    __shared__ float sred[256];
    __shared__ int   sidx[256];

    float mx = -3.402823466e38f;
    for (int a = tid; a < A_; a += 256) mx = fmaxf(mx, row[a]);
    sred[tid] = mx; __syncthreads();
    for (int s = 128; s; s >>= 1) {
        if (tid < s) sred[tid] = fmaxf(sred[tid], sred[tid + s]);
        __syncthreads();
    }
    const float rmax = sred[0]; __syncthreads();

    float sum = 0.f;
    for (int a = tid; a < A_; a += 256) sum += expf(row[a] - rmax);
    sred[tid] = sum; __syncthreads();
    for (int s = 128; s; s >>= 1) {
        if (tid < s) sred[tid] += sred[tid + s];
        __syncthreads();
    }
    const float rsum = sred[0]; __syncthreads();

    float bestv = -3.402823466e38f;
    int   besti = A_;
    for (int a = tid; a < A_; a += 256) {
        float p = expf(row[a] - rmax) / rsum;
        float v = p + gumbel_at((uint32_t)(b * A_ + a));
        if (v > bestv) { bestv = v; besti = a; }   // strided: keeps lowest a on ties
    }
    sred[tid] = bestv; sidx[tid] = besti; __syncthreads();
    for (int s = 128; s; s >>= 1) {
        if (tid < s) {
            float v2 = sred[tid + s]; int i2 = sidx[tid + s];
            if (v2 > sred[tid] || (v2 == sred[tid] && i2 < sidx[tid])) {
                sred[tid] = v2; sidx[tid] = i2;
            }
        }
        __syncthreads();
    }
    if (tid == 0) {
        const int a = sidx[0];
        g_action[b] = a;
        float p = expf(row[a] - rmax) / rsum;
        p = fminf(fmaxf(p, 1e-7f), 1.0f - 1e-7f);
        g_rowloss[b] = -logf(p);
    }
}

__global__ void finalize_kernel(float* __restrict__ out, int out_size) {
    const int tid = threadIdx.x;
    __shared__ float red[256];
    red[tid] = g_rowloss[tid];
    __syncthreads();
    for (int s = 128; s; s >>= 1) {
        if (tid < s) red[tid] += red[tid + s];
        __syncthreads();
    }
    const float loss = red[0] / (float)B_;

    if (out_size == 1) {
        if (tid == 0) out[0] = loss;
        return;
    }
    if (tid < B_ && tid < out_size) out[tid] = (float)g_action[tid];
    if (tid == 0 && out_size > B_) out[B_] = loss;
    for (int i = B_ + 1 + tid; i < out_size; i += 256) out[i] = 0.0f;
}

// ---------------- launch -----------------------------------------------------
extern "C" void kernel_launch(void* const* d_in, const int* in_sizes, int n_in,
                              void* d_out, int out_size) {
    const float* inputs = (const float*)d_in[0];
    const float* Wx     = (const float*)d_in[1];
    const float* Wh     = (const float*)d_in[2];
    const float* b_rnn  = (const float*)d_in[3];
    const float* W1     = (const float*)d_in[4];
    const float* b1     = (const float*)d_in[5];
    const float* W2     = (const float*)d_in[6];
    const float* b2     = (const float*)d_in[7];

    float *xw, *hh, *hid, *logits;
    cudaGetSymbolAddress((void**)&xw,     g_xw);
    cudaGetSymbolAddress((void**)&hh,     g_h);
    cudaGetSymbolAddress((void**)&hid,    g_hid);
    cudaGetSymbolAddress((void**)&logits, g_logits);
    float* h0 = hh;
    float* h1 = hh + (size_t)B_ * H_;

    zero_h0_kernel<<<(B_ * H_ + 255) / 256, 256>>>();

    // xw = inputs @ Wx + b_rnn   (M=65536, N=1024, K=512)
    sgemm_kernel<128, 128, 16, 8, 8, 256, false>
        <<<dim3(H_ / 128, (B_ * T_) / 128), 256>>>(
            B_ * T_, H_, F_, inputs, F_, Wx, H_,
            nullptr, 0, b_rnn, xw, H_);

    // recurrence: h_{t+1} = relu(xw_t + h_t @ Wh)
    for (int t = 0; t < T_; ++t) {
        const float* hin  = (t & 1) ? h1 : h0;
        float*       hout = (t & 1) ? h0 : h1;
        sgemm_kernel<32, 64, 16, 4, 4, 128, true>
            <<<dim3(H_ / 64, B_ / 32), 128>>>(
                B_, H_, H_, hin, H_, Wh, H_,
                xw + (long)t * H_, (long)T_ * H_, nullptr, hout, H_);
    }
    // h_last is in h0 after 256 steps

    // hid = relu(h_last @ W1 + b1)
    sgemm_kernel<32, 64, 16, 4, 4, 128, true>
        <<<dim3(H_ / 64, B_ / 32), 128>>>(
            B_, H_, H_, h0, H_, W1, H_, nullptr, 0, b1, hid, H_);

    // logits = hid @ W2 + b2   (N=1000, ragged)
    sgemm_kernel<32, 64, 16, 4, 4, 128, false>
        <<<dim3((A_ + 63) / 64, B_ / 32), 128>>>(
            B_, A_, H_, hid, H_, W2, A_, nullptr, 0, b2, logits, A_);

    sample_kernel<<<B_, 256>>>();
    finalize_kernel<<<1, 256>>>((float*)d_out, out_size);
}

// round 4
// speedup vs baseline: 1.1025x; 1.1025x over previous
#include <cuda_runtime.h>
#include <cstdint>

#define B_ 256
#define T_ 256
#define F_ 512
#define H_ 1024
#define A_ 1000

// recurrence tiling: 128 persistent blocks = 4 row-groups x 32 col-groups
#define NBLK 128
#define BMr  64
#define BNr  32
#define BKr  16

// ---------------- scratch (static device globals; no allocation) -------------
__device__ float g_xw[(size_t)B_ * T_ * H_];   // input projection [B][T][H]
__device__ float g_h[2][B_ * H_];              // ping-pong hidden state
__device__ float g_hid[B_ * H_];
__device__ float g_logits[B_ * A_];
__device__ int   g_action[B_];
__device__ float g_rowloss[B_];

// grid barrier state
__device__ unsigned g_cnt = 0;
__device__ volatile unsigned g_gen = 0;

// ---------------- packed fp32x2 FMA helpers (Blackwell) ----------------------
__device__ __forceinline__ unsigned long long pack2(float lo, float hi) {
    unsigned long long r;
    asm("mov.b64 %0, {%1, %2};" : "=l"(r) : "f"(lo), "f"(hi));
    return r;
}
__device__ __forceinline__ void unpack2(unsigned long long v, float& lo, float& hi) {
    asm("mov.b64 {%0, %1}, %2;" : "=f"(lo), "=f"(hi) : "l"(v));
}
__device__ __forceinline__ void ffma2(unsigned long long& d, unsigned long long a,
                                      unsigned long long b) {
    asm("fma.rn.f32x2 %0, %1, %2, %0;" : "+l"(d) : "l"(a), "l"(b));
}

// ---------------- grid-wide barrier (all NBLK blocks co-resident) ------------
__device__ __forceinline__ void grid_sync() {
    __syncthreads();
    if (threadIdx.x == 0) {
        __threadfence();
        unsigned gen = g_gen;
        unsigned old = atomicAdd(&g_cnt, 1u);
        if (old == NBLK - 1) {
            g_cnt = 0;
            __threadfence();
            g_gen = gen + 1;
        } else {
            while (g_gen == gen) { __nanosleep(32); }
            __threadfence();
        }
    }
    __syncthreads();
}

// ---------------- persistent recurrence kernel -------------------------------
// Each block owns output tile rows [bm, bm+64), cols [bn, bn+32).
// Weight slab Wh[:, bn..bn+32) stays in SMEM for all steps (128 KB).
// h-chunk staging is stored DUPLICATED as u64 (h,h) pairs so the inner loop is
// pure {LDS.64 b-pair, 2x LDS.128 dup-a, 4x FFMA2} -- no MOV duplication.

// 64x32x1024 tile GEMM from global hrow (per-thread staging pointer) against
// the smem slab; acc[i] accumulates (col n0,n1) of row (ty*4+i).
__device__ __forceinline__ void tile_gemm_1024(
    const float* __restrict__ hrow,          // &hin[(bm+m_l)*H + kq]
    const float* __restrict__ Whs,           // [1024][32]
    unsigned long long* __restrict__ hsd,    // [2][16][64]
    int ty, int tx, int m_l, int kq,
    unsigned long long acc[4])
{
    // preload chunk 0
    float4 pre = __ldcg((const float4*)hrow);
    {
        unsigned long long* d = &hsd[(0 * BKr + kq) * BMr + m_l];
        d[0 * BMr] = pack2(pre.x, pre.x);
        d[1 * BMr] = pack2(pre.y, pre.y);
        d[2 * BMr] = pack2(pre.z, pre.z);
        d[3 * BMr] = pack2(pre.w, pre.w);
    }
    __syncthreads();

    const int nCh = H_ / BKr;  // 64
    for (int kt = 0; kt < nCh; ++kt) {
        const int buf = kt & 1;
        if (kt + 1 < nCh)
            pre = __ldcg((const float4*)(hrow + (kt + 1) * BKr));

        const unsigned long long* as = &hsd[(buf * BKr) * BMr + ty * 4];
        const float* ws = &Whs[(kt * BKr) * BNr + tx * 2];
#pragma unroll
        for (int kk = 0; kk < BKr; ++kk) {
            unsigned long long bp = *(const unsigned long long*)(ws + kk * BNr);
            ulonglong2 a01 = *(const ulonglong2*)(as + kk * BMr);
            ulonglong2 a23 = *(const ulonglong2*)(as + kk * BMr + 2);
            ffma2(acc[0], a01.x, bp);
            ffma2(acc[1], a01.y, bp);
            ffma2(acc[2], a23.x, bp);
            ffma2(acc[3], a23.y, bp);
        }

        if (kt + 1 < nCh) {
            unsigned long long* d = &hsd[(((buf ^ 1) * BKr) + kq) * BMr + m_l];
            d[0 * BMr] = pack2(pre.x, pre.x);
            d[1 * BMr] = pack2(pre.y, pre.y);
            d[2 * BMr] = pack2(pre.z, pre.z);
            d[3 * BMr] = pack2(pre.w, pre.w);
        }
        __syncthreads();
    }
}

__global__ void __launch_bounds__(256, 1)
rnn_recur(const float* __restrict__ xw, const float* __restrict__ Wh,
          const float* __restrict__ W1, const float* __restrict__ b1,
          float* __restrict__ hb0, float* __restrict__ hb1,
          float* __restrict__ hid)
{
    extern __shared__ float sm[];
    float* Whs = sm;                                                  // 1024*32 floats
    unsigned long long* hsd = (unsigned long long*)(sm + H_ * BNr);   // [2][16][64]

    const int tid = threadIdx.x;
    const int r = blockIdx.x >> 5;      // 0..3
    const int c = blockIdx.x & 31;      // 0..31
    const int bm = r * BMr, bn = c * BNr;
    const int tx = tid & 15;            // cols bn + tx*2, +1
    const int ty = tid >> 4;            // rows bm + ty*4 .. +3
    const int m_l = tid >> 2;           // staging row 0..63
    const int kq  = (tid & 3) * 4;      // staging k offset {0,4,8,12}

    // load Wh slab into smem (stays for all 255 steps)
    for (int v = tid; v < H_ * BNr / 4; v += 256) {
        int k = v >> 3, nq = v & 7;
        float4 w = __ldg((const float4*)&Wh[(long)k * H_ + bn + nq * 4]);
        *(float4*)&Whs[k * BNr + nq * 4] = w;
    }

    // t=1: h1 = relu(xw[:,0,:])  (h0 == 0)
#pragma unroll
    for (int i = 0; i < 4; ++i) {
        int m = bm + ty * 4 + i;
        float2 v = *(const float2*)&xw[((long)m * T_ + 0) * H_ + bn + tx * 2];
        float2 o = { fmaxf(v.x, 0.f), fmaxf(v.y, 0.f) };
        *(float2*)&hb1[(long)m * H_ + bn + tx * 2] = o;
    }
    grid_sync();

    for (int t = 1; t < T_; ++t) {
        const float* hin = (t & 1) ? hb1 : hb0;
        float* hout      = (t & 1) ? hb0 : hb1;

        unsigned long long acc[4] = {0ull, 0ull, 0ull, 0ull};
        tile_gemm_1024(&hin[(long)(bm + m_l) * H_ + kq], Whs, hsd,
                       ty, tx, m_l, kq, acc);

        // epilogue: hout = relu(acc + xw[:,t,:])
#pragma unroll
        for (int i = 0; i < 4; ++i) {
            int m = bm + ty * 4 + i;
            float2 xv = *(const float2*)&xw[((long)m * T_ + t) * H_ + bn + tx * 2];
            float lo, hi; unpack2(acc[i], lo, hi);
            float2 o = { fmaxf(lo + xv.x, 0.f), fmaxf(hi + xv.y, 0.f) };
            *(float2*)&hout[(long)m * H_ + bn + tx * 2] = o;
        }
        grid_sync();
    }
    // h_last = h_256 lives in hb0 (t=255 wrote hout=hb0)

    // fused dense1: hid = relu(h_last @ W1 + b1). Swap slab to W1.
    for (int v = tid; v < H_ * BNr / 4; v += 256) {
        int k = v >> 3, nq = v & 7;
        float4 w = __ldg((const float4*)&W1[(long)k * H_ + bn + nq * 4]);
        *(float4*)&Whs[k * BNr + nq * 4] = w;
    }
    __syncthreads();
    {
        unsigned long long acc[4] = {0ull, 0ull, 0ull, 0ull};
        tile_gemm_1024(&hb0[(long)(bm + m_l) * H_ + kq], Whs, hsd,
                       ty, tx, m_l, kq, acc);
        float2 bb = *(const float2*)&b1[bn + tx * 2];
#pragma unroll
        for (int i = 0; i < 4; ++i) {
            int m = bm + ty * 4 + i;
            float lo, hi; unpack2(acc[i], lo, hi);
            float2 o = { fmaxf(lo + bb.x, 0.f), fmaxf(hi + bb.y, 0.f) };
            *(float2*)&hid[(long)m * H_ + bn + tx * 2] = o;
        }
    }
}

// ---------------- double-buffered SGEMM template (dup-A, no pack MOVs) -------
// C[M,N] = act( A[M,K] @ B[K,N] + bias[n]? ),  row-major.
template <int BM, int BN, int BK, int TM, int TN, int THREADS, bool RELU>
__global__ void __launch_bounds__(THREADS)
sgemm_kernel(int M, int N, int K,
             const float* __restrict__ A, int lda,
             const float* __restrict__ Bm, int ldb,
             const float* __restrict__ bias,
             float* __restrict__ C, int ldc)
{
    static_assert(TN % 4 == 0 && TM % 2 == 0, "");
    constexpr int TX = BN / TN;
    constexpr int TY = BM / TM;
    static_assert(TX * TY == THREADS, "");

    __shared__ __align__(16) unsigned long long As[2][BK][BM];  // duplicated pairs
    __shared__ __align__(16) float Bs[2][BK][BN];

    const int tid = threadIdx.x;
    const int tx  = tid % TX;
    const int ty  = tid / TX;
    const int bm  = blockIdx.y * BM;
    const int bn  = blockIdx.x * BN;

    constexpr int A_VECS = BM * BK / 4;
    constexpr int A_PER  = A_VECS / THREADS;
    constexpr int B_VECS = BK * BN / 4;
    constexpr int B_PER  = B_VECS / THREADS;
    static_assert(A_VECS % THREADS == 0 && B_VECS % THREADS == 0, "");

    float4 aReg[A_PER];
    float4 bReg[B_PER];

    auto loadA = [&](int k0) {
#pragma unroll
        for (int i = 0; i < A_PER; ++i) {
            int v   = tid + i * THREADS;
            int row = v / (BK / 4);
            int kc  = (v % (BK / 4)) * 4;
            aReg[i] = *reinterpret_cast<const float4*>(
                &A[(long)(bm + row) * lda + k0 + kc]);
        }
    };
    auto loadB = [&](int k0) {
#pragma unroll
        for (int i = 0; i < B_PER; ++i) {
            int v    = tid + i * THREADS;
            int krow = v / (BN / 4);
            int nc   = (v % (BN / 4)) * 4;
            int col  = bn + nc;
            if (col < N)
                bReg[i] = *reinterpret_cast<const float4*>(
                    &Bm[(long)(k0 + krow) * ldb + col]);
            else
                bReg[i] = make_float4(0.f, 0.f, 0.f, 0.f);
        }
    };
    auto storeA = [&](int buf) {
#pragma unroll
        for (int i = 0; i < A_PER; ++i) {
            int v   = tid + i * THREADS;
            int row = v / (BK / 4);
            int kc  = (v % (BK / 4)) * 4;
            As[buf][kc + 0][row] = pack2(aReg[i].x, aReg[i].x);
            As[buf][kc + 1][row] = pack2(aReg[i].y, aReg[i].y);
            As[buf][kc + 2][row] = pack2(aReg[i].z, aReg[i].z);
            As[buf][kc + 3][row] = pack2(aReg[i].w, aReg[i].w);
        }
    };
    auto storeB = [&](int buf) {
#pragma unroll
        for (int i = 0; i < B_PER; ++i) {
            int v    = tid + i * THREADS;
            int krow = v / (BN / 4);
            int nc   = (v % (BN / 4)) * 4;
            *reinterpret_cast<float4*>(&Bs[buf][krow][nc]) = bReg[i];
        }
    };

    unsigned long long acc[TM][TN / 2];
#pragma unroll
    for (int i = 0; i < TM; ++i)
#pragma unroll
        for (int j = 0; j < TN / 2; ++j) acc[i][j] = 0ull;

    loadA(0); loadB(0);
    storeA(0); storeB(0);
    __syncthreads();

    const int nTiles = K / BK;
    for (int kt = 0; kt < nTiles; ++kt) {
        const int cur = kt & 1, nxt = cur ^ 1;
        if (kt + 1 < nTiles) { loadA((kt + 1) * BK); loadB((kt + 1) * BK); }

#pragma unroll
        for (int kk = 0; kk < BK; ++kk) {
            unsigned long long a2[TM];
#pragma unroll
            for (int i = 0; i < TM; i += 2) {
                ulonglong2 t = *reinterpret_cast<const ulonglong2*>(
                    &As[cur][kk][ty * TM + i]);
                a2[i] = t.x; a2[i + 1] = t.y;
            }
            unsigned long long b2[TN / 2];
#pragma unroll
            for (int j = 0; j < TN / 4; ++j) {
                ulonglong2 bv = *reinterpret_cast<const ulonglong2*>(
                    &Bs[cur][kk][tx * TN + 4 * j]);
                b2[2 * j] = bv.x; b2[2 * j + 1] = bv.y;
            }
#pragma unroll
            for (int i = 0; i < TM; ++i)
#pragma unroll
                for (int j = 0; j < TN / 2; ++j) ffma2(acc[i][j], a2[i], b2[j]);
        }

        if (kt + 1 < nTiles) { storeA(nxt); storeB(nxt); }
        __syncthreads();
    }

    // epilogue
#pragma unroll
    for (int i = 0; i < TM; ++i) {
        const int m = bm + ty * TM + i;
#pragma unroll
        for (int j = 0; j < TN / 2; ++j) {
            float lo, hi;
            unpack2(acc[i][j], lo, hi);
            float v[2] = {lo, hi};
            const int n0 = bn + tx * TN + 2 * j;
#pragma unroll
            for (int e = 0; e < 2; ++e) {
                const int n = n0 + e;
                if (n < N) {
                    float cv = v[e];
                    if (bias) cv += bias[n];
                    if (RELU) cv = fmaxf(cv, 0.0f);
                    C[(long)m * ldc + n] = cv;
                }
            }
        }
    }
}

// ---------------- threefry2x32 / JAX gumbel ----------------------------------
__device__ __forceinline__ float gumbel_at(uint32_t idx) {
    const uint32_t k0 = 0u, k1 = 42u;
    const uint32_t ks2 = k0 ^ k1 ^ 0x1BD11BDAu;
    uint32_t x0 = k0;
    uint32_t x1 = idx + k1;
#define RND(r) { x0 += x1; x1 = ((x1 << (r)) | (x1 >> (32 - (r)))) ^ x0; }
    RND(13) RND(15) RND(26) RND(6)   x0 += k1;  x1 += ks2 + 1u;
    RND(17) RND(29) RND(16) RND(24)  x0 += ks2; x1 += k0 + 2u;
    RND(13) RND(15) RND(26) RND(6)   x0 += k0;  x1 += k1 + 3u;
    RND(17) RND(29) RND(16) RND(24)  x0 += k1;  x1 += ks2 + 4u;
    RND(13) RND(15) RND(26) RND(6)   x0 += ks2; x1 += k0 + 5u;
#undef RND
    const uint32_t bits = x0 ^ x1;
    float f = __uint_as_float((bits >> 9) | 0x3f800000u) - 1.0f;
    float u = fmaxf(f, 1.17549435e-38f);
    return -logf(-logf(u));
}

// ---------------- softmax+sample, finalize -----------------------------------
__global__ void sample_kernel() {
    const int b = blockIdx.x;
    const float* __restrict__ row = g_logits + (long)b * A_;
    const int tid = threadIdx.x;
    __shared__ float sred[256];
    __shared__ int   sidx[256];

    float mx = -3.402823466e38f;
    for (int a = tid; a < A_; a += 256) mx = fmaxf(mx, row[a]);
    sred[tid] = mx; __syncthreads();
    for (int s = 128; s; s >>= 1) {
        if (tid < s) sred[tid] = fmaxf(sred[tid], sred[tid + s]);
        __syncthreads();
    }
    const float rmax = sred[0]; __syncthreads();

    float sum = 0.f;
    for (int a = tid; a < A_; a += 256) sum += expf(row[a] - rmax);
    sred[tid] = sum; __syncthreads();
    for (int s = 128; s; s >>= 1) {
        if (tid < s) sred[tid] += sred[tid + s];
        __syncthreads();
    }
    const float rsum = sred[0]; __syncthreads();

    float bestv = -3.402823466e38f;
    int   besti = A_;
    for (int a = tid; a < A_; a += 256) {
        float p = expf(row[a] - rmax) / rsum;
        float v = p + gumbel_at((uint32_t)(b * A_ + a));
        if (v > bestv) { bestv = v; besti = a; }
    }
    sred[tid] = bestv; sidx[tid] = besti; __syncthreads();
    for (int s = 128; s; s >>= 1) {
        if (tid < s) {
            float v2 = sred[tid + s]; int i2 = sidx[tid + s];
            if (v2 > sred[tid] || (v2 == sred[tid] && i2 < sidx[tid])) {
                sred[tid] = v2; sidx[tid] = i2;
            }
        }
        __syncthreads();
    }
    if (tid == 0) {
        const int a = sidx[0];
        g_action[b] = a;
        float p = expf(row[a] - rmax) / rsum;
        p = fminf(fmaxf(p, 1e-7f), 1.0f - 1e-7f);
        g_rowloss[b] = -logf(p);
    }
}

__global__ void finalize_kernel(float* __restrict__ out, int out_size) {
    const int tid = threadIdx.x;
    __shared__ float red[256];
    red[tid] = g_rowloss[tid];
    __syncthreads();
    for (int s = 128; s; s >>= 1) {
        if (tid < s) red[tid] += red[tid + s];
        __syncthreads();
    }
    const float loss = red[0] / (float)B_;

    if (out_size == 1) {
        if (tid == 0) out[0] = loss;
        return;
    }
    if (tid < B_ && tid < out_size) out[tid] = (float)g_action[tid];
    if (tid == 0 && out_size > B_) out[B_] = loss;
    for (int i = B_ + 1 + tid; i < out_size; i += 256) out[i] = 0.0f;
}

// ---------------- launch -----------------------------------------------------
extern "C" void kernel_launch(void* const* d_in, const int* in_sizes, int n_in,
                              void* d_out, int out_size) {
    const float* inputs = (const float*)d_in[0];
    const float* Wx     = (const float*)d_in[1];
    const float* Wh     = (const float*)d_in[2];
    const float* b_rnn  = (const float*)d_in[3];
    const float* W1     = (const float*)d_in[4];
    const float* b1     = (const float*)d_in[5];
    const float* W2     = (const float*)d_in[6];
    const float* b2     = (const float*)d_in[7];

    float *xw, *hh, *hid, *logits;
    cudaGetSymbolAddress((void**)&xw,     g_xw);
    cudaGetSymbolAddress((void**)&hh,     g_h);
    cudaGetSymbolAddress((void**)&hid,    g_hid);
    cudaGetSymbolAddress((void**)&logits, g_logits);
    float* hb0 = hh;
    float* hb1 = hh + (size_t)B_ * H_;

    // xw = inputs @ Wx + b_rnn   (M=65536, N=1024, K=512)
    sgemm_kernel<128, 128, 16, 8, 8, 256, false>
        <<<dim3(H_ / 128, (B_ * T_) / 128), 256>>>(
            B_ * T_, H_, F_, inputs, F_, Wx, H_, b_rnn, xw, H_);

    // persistent recurrence + fused dense1
    const int smem = H_ * BNr * 4 + 2 * BKr * BMr * 8;  // 131072 + 16384
    cudaFuncSetAttribute(rnn_recur, cudaFuncAttributeMaxDynamicSharedMemorySize, smem);
    rnn_recur<<<NBLK, 256, smem>>>(xw, Wh, W1, b1, hb0, hb1, hid);

    // logits = hid @ W2 + b2   (N=1000, ragged)
    sgemm_kernel<32, 64, 16, 4, 4, 128, false>
        <<<dim3((A_ + 63) / 64, B_ / 32), 128>>>(
            B_, A_, H_, hid, H_, W2, A_, b2, logits, A_);

    sample_kernel<<<B_, 256>>>();
    finalize_kernel<<<1, 256>>>((float*)d_out, out_size);
}

// round 5
// speedup vs baseline: 1.3471x; 1.2218x over previous
#include <cuda_runtime.h>
#include <cstdint>

#define B_ 256
#define T_ 256
#define F_ 512
#define H_ 1024
#define A_ 1000

// recurrence: 128 blocks = 4 row-groups(64) x 8 col-groups(128) x 4 k-splits(256)
#define NBLK 128
#define RROWS 64
#define RCOLS 128
#define RK    256
#define BKr   16
#define SPAD  66   // staging row pitch in u64 (pad vs 64 to cut bank conflicts)

// ---------------- scratch (static device globals; no allocation) -------------
__device__ float g_xw[(size_t)B_ * T_ * H_];     // input projection [B][T][H]
__device__ float g_hbuf[B_ * H_];                // hidden state
__device__ float g_part[4][B_ * H_];             // k-split partials [q][m][n]
__device__ float g_hid[B_ * H_];
__device__ float g_logits[B_ * A_];
__device__ int   g_action[B_];
__device__ float g_rowloss[B_];

// grid barrier state
__device__ unsigned g_cnt = 0;
__device__ volatile unsigned g_gen = 0;

// ---------------- packed fp32x2 FMA helpers (Blackwell) ----------------------
__device__ __forceinline__ unsigned long long pack2(float lo, float hi) {
    unsigned long long r;
    asm("mov.b64 %0, {%1, %2};" : "=l"(r) : "f"(lo), "f"(hi));
    return r;
}
__device__ __forceinline__ void unpack2(unsigned long long v, float& lo, float& hi) {
    asm("mov.b64 {%0, %1}, %2;" : "=f"(lo), "=f"(hi) : "l"(v));
}
__device__ __forceinline__ void ffma2(unsigned long long& d, unsigned long long a,
                                      unsigned long long b) {
    asm("fma.rn.f32x2 %0, %1, %2, %0;" : "+l"(d) : "l"(a), "l"(b));
}

// ---------------- grid-wide barrier (all NBLK blocks co-resident) ------------
__device__ __forceinline__ void grid_sync() {
    __syncthreads();
    if (threadIdx.x == 0) {
        __threadfence();
        unsigned gen = g_gen;
        unsigned old = atomicAdd(&g_cnt, 1u);
        if (old == NBLK - 1) {
            g_cnt = 0;
            __threadfence();
            g_gen = gen + 1;
        } else {
            while (g_gen == gen) { __nanosleep(16); }
            __threadfence();
        }
    }
    __syncthreads();
}

// ---------------- persistent recurrence kernel -------------------------------
// Block (r,c,q): rows [r*64,+64), cols [c*128,+128), k in [q*256,+256).
// Slab Wh[k-range][col-range] (128 KB) resident in smem for all 255 steps.
// Per thread: 4 rows x 8 cols = 16 outputs (acc as 16 u64 fp32x2 pairs).
// Inner k: 2x LDS.128 (dup'd a) + 2x LDS.128 (b pairs) + 16 FFMA2.

struct RecurSmem {
    float Whs[RK * RCOLS];                       // 128 KB slab
    unsigned long long hsd[2 * BKr * SPAD];      // staging, dup'd (a,a) pairs
};

// one k-split partial tile GEMM: acc[i][jp] += h[.][k] * Whs
__device__ __forceinline__ void tile_gemm_part(
    const float* __restrict__ hrow,              // &h[(bm+m_l)*H + bk + kq]
    const float* __restrict__ Whs,
    unsigned long long* __restrict__ hsd,
    int ty, int tx, int m_l, int kq,
    unsigned long long acc[4][4])
{
    float4 pre = __ldcg((const float4*)hrow);
    {
        unsigned long long* d = &hsd[(0 * BKr + kq) * SPAD + m_l];
        d[0 * SPAD] = pack2(pre.x, pre.x);
        d[1 * SPAD] = pack2(pre.y, pre.y);
        d[2 * SPAD] = pack2(pre.z, pre.z);
        d[3 * SPAD] = pack2(pre.w, pre.w);
    }
    __syncthreads();

    const int nCh = RK / BKr;  // 16
    for (int kt = 0; kt < nCh; ++kt) {
        const int buf = kt & 1;
        if (kt + 1 < nCh)
            pre = __ldcg((const float4*)(hrow + (kt + 1) * BKr));

        const unsigned long long* as = &hsd[(buf * BKr) * SPAD + ty * 4];
        const float* ws = &Whs[(kt * BKr) * RCOLS + tx * 8];
#pragma unroll
        for (int kk = 0; kk < BKr; ++kk) {
            ulonglong2 a01 = *(const ulonglong2*)(as + kk * SPAD);
            ulonglong2 a23 = *(const ulonglong2*)(as + kk * SPAD + 2);
            ulonglong2 b01 = *(const ulonglong2*)(ws + kk * RCOLS);
            ulonglong2 b23 = *(const ulonglong2*)(ws + kk * RCOLS + 4);
            ffma2(acc[0][0], a01.x, b01.x); ffma2(acc[0][1], a01.x, b01.y);
            ffma2(acc[0][2], a01.x, b23.x); ffma2(acc[0][3], a01.x, b23.y);
            ffma2(acc[1][0], a01.y, b01.x); ffma2(acc[1][1], a01.y, b01.y);
            ffma2(acc[1][2], a01.y, b23.x); ffma2(acc[1][3], a01.y, b23.y);
            ffma2(acc[2][0], a23.x, b01.x); ffma2(acc[2][1], a23.x, b01.y);
            ffma2(acc[2][2], a23.x, b23.x); ffma2(acc[2][3], a23.x, b23.y);
            ffma2(acc[3][0], a23.y, b01.x); ffma2(acc[3][1], a23.y, b01.y);
            ffma2(acc[3][2], a23.y, b23.x); ffma2(acc[3][3], a23.y, b23.y);
        }

        if (kt + 1 < nCh) {
            unsigned long long* d = &hsd[(((buf ^ 1) * BKr) + kq) * SPAD + m_l];
            d[0 * SPAD] = pack2(pre.x, pre.x);
            d[1 * SPAD] = pack2(pre.y, pre.y);
            d[2 * SPAD] = pack2(pre.z, pre.z);
            d[3 * SPAD] = pack2(pre.w, pre.w);
        }
        __syncthreads();
    }
}

__device__ __forceinline__ void store_partials(
    unsigned long long acc[4][4], float* __restrict__ pq,
    int bm, int bn, int ty, int tx)
{
#pragma unroll
    for (int i = 0; i < 4; ++i) {
        const int m = bm + ty * 4 + i;
        float v0, v1, v2, v3, v4, v5, v6, v7;
        unpack2(acc[i][0], v0, v1);
        unpack2(acc[i][1], v2, v3);
        unpack2(acc[i][2], v4, v5);
        unpack2(acc[i][3], v6, v7);
        float4 lo = make_float4(v0, v1, v2, v3);
        float4 hi = make_float4(v4, v5, v6, v7);
        __stcg((float4*)&pq[(long)m * H_ + bn + tx * 8], lo);
        __stcg((float4*)&pq[(long)m * H_ + bn + tx * 8 + 4], hi);
    }
}

__global__ void __launch_bounds__(256, 1)
rnn_recur(const float* __restrict__ xw, const float* __restrict__ Wh,
          const float* __restrict__ W1, const float* __restrict__ b1,
          float* __restrict__ h, float* __restrict__ hid)
{
    extern __shared__ __align__(16) char smraw[];
    RecurSmem* sm = (RecurSmem*)smraw;

    const int tid = threadIdx.x;
    const int bid = blockIdx.x;
    const int q = bid & 3;
    const int c = (bid >> 2) & 7;
    const int r = bid >> 5;
    const int bm = r * RROWS, bn = c * RCOLS, bk = q * RK;
    const int tx = tid & 15;        // cols bn + tx*8 .. +7
    const int ty = tid >> 4;        // rows bm + ty*4 .. +3
    const int m_l = tid >> 2;       // staging row 0..63
    const int kq  = (tid & 3) * 4;  // staging k offset {0,4,8,12}
    const int gtid = bid * 256 + tid;

    // load Wh slab [bk..bk+256) x [bn..bn+128) into smem (resident all steps)
    for (int v = tid; v < RK * RCOLS / 4; v += 256) {
        int k = v >> 5, nq = v & 31;
        float4 w = __ldg((const float4*)&Wh[(long)(bk + k) * H_ + bn + nq * 4]);
        *(float4*)&sm->Whs[k * RCOLS + nq * 4] = w;
    }

    // h_1 = relu(xw[:,0,:])  (h_0 == 0) — all 32768 threads, 2 float4 each
#pragma unroll
    for (int i = 0; i < 2; ++i) {
        int idx4 = gtid * 2 + i;                 // 0..65535
        int m = idx4 >> 8, n4 = (idx4 & 255) * 4;
        float4 v = __ldg((const float4*)&xw[((long)m * T_ + 0) * H_ + n4]);
        v.x = fmaxf(v.x, 0.f); v.y = fmaxf(v.y, 0.f);
        v.z = fmaxf(v.z, 0.f); v.w = fmaxf(v.w, 0.f);
        __stcg((float4*)&h[(long)m * H_ + n4], v);
    }
    grid_sync();

    for (int t = 1; t < T_; ++t) {
        // partial GEMM over this block's k-range
        unsigned long long acc[4][4];
#pragma unroll
        for (int i = 0; i < 4; ++i)
#pragma unroll
            for (int j = 0; j < 4; ++j) acc[i][j] = 0ull;

        tile_gemm_part(&h[(long)(bm + m_l) * H_ + bk + kq], sm->Whs, sm->hsd,
                       ty, tx, m_l, kq, acc);
        store_partials(acc, g_part[q], bm, bn, ty, tx);
        grid_sync();

        // reduce: h = relu(xw[:,t,:] + sum_q partial_q)
#pragma unroll
        for (int i = 0; i < 2; ++i) {
            int idx4 = gtid * 2 + i;
            int m = idx4 >> 8, n4 = (idx4 & 255) * 4;
            long off = (long)m * H_ + n4;
            float4 s = __ldg((const float4*)&xw[((long)m * T_ + t) * H_ + n4]);
            float4 p0 = __ldcg((const float4*)&g_part[0][off]);
            float4 p1 = __ldcg((const float4*)&g_part[1][off]);
            float4 p2 = __ldcg((const float4*)&g_part[2][off]);
            float4 p3 = __ldcg((const float4*)&g_part[3][off]);
            s.x = fmaxf(s.x + p0.x + p1.x + p2.x + p3.x, 0.f);
            s.y = fmaxf(s.y + p0.y + p1.y + p2.y + p3.y, 0.f);
            s.z = fmaxf(s.z + p0.z + p1.z + p2.z + p3.z, 0.f);
            s.w = fmaxf(s.w + p0.w + p1.w + p2.w + p3.w, 0.f);
            __stcg((float4*)&h[off], s);
        }
        grid_sync();
    }
    // h now holds h_last (h_256)

    // fused dense1: hid = relu(h_last @ W1 + b1) — swap slab to W1
    for (int v = tid; v < RK * RCOLS / 4; v += 256) {
        int k = v >> 5, nq = v & 31;
        float4 w = __ldg((const float4*)&W1[(long)(bk + k) * H_ + bn + nq * 4]);
        *(float4*)&sm->Whs[k * RCOLS + nq * 4] = w;
    }
    __syncthreads();
    {
        unsigned long long acc[4][4];
#pragma unroll
        for (int i = 0; i < 4; ++i)
#pragma unroll
            for (int j = 0; j < 4; ++j) acc[i][j] = 0ull;
        tile_gemm_part(&h[(long)(bm + m_l) * H_ + bk + kq], sm->Whs, sm->hsd,
                       ty, tx, m_l, kq, acc);
        store_partials(acc, g_part[q], bm, bn, ty, tx);
        grid_sync();
#pragma unroll
        for (int i = 0; i < 2; ++i) {
            int idx4 = gtid * 2 + i;
            int m = idx4 >> 8, n4 = (idx4 & 255) * 4;
            long off = (long)m * H_ + n4;
            float4 s = __ldg((const float4*)&b1[n4]);
            float4 p0 = __ldcg((const float4*)&g_part[0][off]);
            float4 p1 = __ldcg((const float4*)&g_part[1][off]);
            float4 p2 = __ldcg((const float4*)&g_part[2][off]);
            float4 p3 = __ldcg((const float4*)&g_part[3][off]);
            s.x = fmaxf(s.x + p0.x + p1.x + p2.x + p3.x, 0.f);
            s.y = fmaxf(s.y + p0.y + p1.y + p2.y + p3.y, 0.f);
            s.z = fmaxf(s.z + p0.z + p1.z + p2.z + p3.z, 0.f);
            s.w = fmaxf(s.w + p0.w + p1.w + p2.w + p3.w, 0.f);
            __stcg((float4*)&hid[off], s);
        }
    }
}

// ---------------- double-buffered SGEMM template (dup-A) ---------------------
template <int BM, int BN, int BK, int TM, int TN, int THREADS, bool RELU>
__global__ void __launch_bounds__(THREADS)
sgemm_kernel(int M, int N, int K,
             const float* __restrict__ A, int lda,
             const float* __restrict__ Bm, int ldb,
             const float* __restrict__ bias,
             float* __restrict__ C, int ldc)
{
    static_assert(TN % 4 == 0 && TM % 2 == 0, "");
    constexpr int TX = BN / TN;
    constexpr int TY = BM / TM;
    static_assert(TX * TY == THREADS, "");

    __shared__ __align__(16) unsigned long long As[2][BK][BM];
    __shared__ __align__(16) float Bs[2][BK][BN];

    const int tid = threadIdx.x;
    const int tx  = tid % TX;
    const int ty  = tid / TX;
    const int bm  = blockIdx.y * BM;
    const int bn  = blockIdx.x * BN;

    constexpr int A_VECS = BM * BK / 4;
    constexpr int A_PER  = A_VECS / THREADS;
    constexpr int B_VECS = BK * BN / 4;
    constexpr int B_PER  = B_VECS / THREADS;
    static_assert(A_VECS % THREADS == 0 && B_VECS % THREADS == 0, "");

    float4 aReg[A_PER];
    float4 bReg[B_PER];

    auto loadA = [&](int k0) {
#pragma unroll
        for (int i = 0; i < A_PER; ++i) {
            int v   = tid + i * THREADS;
            int row = v / (BK / 4);
            int kc  = (v % (BK / 4)) * 4;
            aReg[i] = *reinterpret_cast<const float4*>(
                &A[(long)(bm + row) * lda + k0 + kc]);
        }
    };
    auto loadB = [&](int k0) {
#pragma unroll
        for (int i = 0; i < B_PER; ++i) {
            int v    = tid + i * THREADS;
            int krow = v / (BN / 4);
            int nc   = (v % (BN / 4)) * 4;
            int col  = bn + nc;
            if (col < N)
                bReg[i] = *reinterpret_cast<const float4*>(
                    &Bm[(long)(k0 + krow) * ldb + col]);
            else
                bReg[i] = make_float4(0.f, 0.f, 0.f, 0.f);
        }
    };
    auto storeA = [&](int buf) {
#pragma unroll
        for (int i = 0; i < A_PER; ++i) {
            int v   = tid + i * THREADS;
            int row = v / (BK / 4);
            int kc  = (v % (BK / 4)) * 4;
            As[buf][kc + 0][row] = pack2(aReg[i].x, aReg[i].x);
            As[buf][kc + 1][row] = pack2(aReg[i].y, aReg[i].y);
            As[buf][kc + 2][row] = pack2(aReg[i].z, aReg[i].z);
            As[buf][kc + 3][row] = pack2(aReg[i].w, aReg[i].w);
        }
    };
    auto storeB = [&](int buf) {
#pragma unroll
        for (int i = 0; i < B_PER; ++i) {
            int v    = tid + i * THREADS;
            int krow = v / (BN / 4);
            int nc   = (v % (BN / 4)) * 4;
            *reinterpret_cast<float4*>(&Bs[buf][krow][nc]) = bReg[i];
        }
    };

    unsigned long long acc[TM][TN / 2];
#pragma unroll
    for (int i = 0; i < TM; ++i)
#pragma unroll
        for (int j = 0; j < TN / 2; ++j) acc[i][j] = 0ull;

    loadA(0); loadB(0);
    storeA(0); storeB(0);
    __syncthreads();

    const int nTiles = K / BK;
    for (int kt = 0; kt < nTiles; ++kt) {
        const int cur = kt & 1, nxt = cur ^ 1;
        if (kt + 1 < nTiles) { loadA((kt + 1) * BK); loadB((kt + 1) * BK); }

#pragma unroll
        for (int kk = 0; kk < BK; ++kk) {
            unsigned long long a2[TM];
#pragma unroll
            for (int i = 0; i < TM; i += 2) {
                ulonglong2 t = *reinterpret_cast<const ulonglong2*>(
                    &As[cur][kk][ty * TM + i]);
                a2[i] = t.x; a2[i + 1] = t.y;
            }
            unsigned long long b2[TN / 2];
#pragma unroll
            for (int j = 0; j < TN / 4; ++j) {
                ulonglong2 bv = *reinterpret_cast<const ulonglong2*>(
                    &Bs[cur][kk][tx * TN + 4 * j]);
                b2[2 * j] = bv.x; b2[2 * j + 1] = bv.y;
            }
#pragma unroll
            for (int i = 0; i < TM; ++i)
#pragma unroll
                for (int j = 0; j < TN / 2; ++j) ffma2(acc[i][j], a2[i], b2[j]);
        }

        if (kt + 1 < nTiles) { storeA(nxt); storeB(nxt); }
        __syncthreads();
    }

#pragma unroll
    for (int i = 0; i < TM; ++i) {
        const int m = bm + ty * TM + i;
#pragma unroll
        for (int j = 0; j < TN / 2; ++j) {
            float lo, hi;
            unpack2(acc[i][j], lo, hi);
            float v[2] = {lo, hi};
            const int n0 = bn + tx * TN + 2 * j;
#pragma unroll
            for (int e = 0; e < 2; ++e) {
                const int n = n0 + e;
                if (n < N) {
                    float cv = v[e];
                    if (bias) cv += bias[n];
                    if (RELU) cv = fmaxf(cv, 0.0f);
                    C[(long)m * ldc + n] = cv;
                }
            }
        }
    }
}

// ---------------- threefry2x32 / JAX gumbel ----------------------------------
__device__ __forceinline__ float gumbel_at(uint32_t idx) {
    const uint32_t k0 = 0u, k1 = 42u;
    const uint32_t ks2 = k0 ^ k1 ^ 0x1BD11BDAu;
    uint32_t x0 = k0;
    uint32_t x1 = idx + k1;
#define RND(r) { x0 += x1; x1 = ((x1 << (r)) | (x1 >> (32 - (r)))) ^ x0; }
    RND(13) RND(15) RND(26) RND(6)   x0 += k1;  x1 += ks2 + 1u;
    RND(17) RND(29) RND(16) RND(24)  x0 += ks2; x1 += k0 + 2u;
    RND(13) RND(15) RND(26) RND(6)   x0 += k0;  x1 += k1 + 3u;
    RND(17) RND(29) RND(16) RND(24)  x0 += k1;  x1 += ks2 + 4u;
    RND(13) RND(15) RND(26) RND(6)   x0 += ks2; x1 += k0 + 5u;
#undef RND
    const uint32_t bits = x0 ^ x1;
    float f = __uint_as_float((bits >> 9) | 0x3f800000u) - 1.0f;
    float u = fmaxf(f, 1.17549435e-38f);
    return -logf(-logf(u));
}

// ---------------- softmax+sample, finalize -----------------------------------
__global__ void sample_kernel() {
    const int b = blockIdx.x;
    const float* __restrict__ row = g_logits + (long)b * A_;
    const int tid = threadIdx.x;
    __shared__ float sred[256];
    __shared__ int   sidx[256];

    float mx = -3.402823466e38f;
    for (int a = tid; a < A_; a += 256) mx = fmaxf(mx, row[a]);
    sred[tid] = mx; __syncthreads();
    for (int s = 128; s; s >>= 1) {
        if (tid < s) sred[tid] = fmaxf(sred[tid], sred[tid + s]);
        __syncthreads();
    }
    const float rmax = sred[0]; __syncthreads();

    float sum = 0.f;
    for (int a = tid; a < A_; a += 256) sum += expf(row[a] - rmax);
    sred[tid] = sum; __syncthreads();
    for (int s = 128; s; s >>= 1) {
        if (tid < s) sred[tid] += sred[tid + s];
        __syncthreads();
    }
    const float rsum = sred[0]; __syncthreads();

    float bestv = -3.402823466e38f;
    int   besti = A_;
    for (int a = tid; a < A_; a += 256) {
        float p = expf(row[a] - rmax) / rsum;
        float v = p + gumbel_at((uint32_t)(b * A_ + a));
        if (v > bestv) { bestv = v; besti = a; }
    }
    sred[tid] = bestv; sidx[tid] = besti; __syncthreads();
    for (int s = 128; s; s >>= 1) {
        if (tid < s) {
            float v2 = sred[tid + s]; int i2 = sidx[tid + s];
            if (v2 > sred[tid] || (v2 == sred[tid] && i2 < sidx[tid])) {
                sred[tid] = v2; sidx[tid] = i2;
            }
        }
        __syncthreads();
    }
    if (tid == 0) {
        const int a = sidx[0];
        g_action[b] = a;
        float p = expf(row[a] - rmax) / rsum;
        p = fminf(fmaxf(p, 1e-7f), 1.0f - 1e-7f);
        g_rowloss[b] = -logf(p);
    }
}

__global__ void finalize_kernel(float* __restrict__ out, int out_size) {
    const int tid = threadIdx.x;
    __shared__ float red[256];
    red[tid] = g_rowloss[tid];
    __syncthreads();
    for (int s = 128; s; s >>= 1) {
        if (tid < s) red[tid] += red[tid + s];
        __syncthreads();
    }
    const float loss = red[0] / (float)B_;

    if (out_size == 1) {
        if (tid == 0) out[0] = loss;
        return;
    }
    if (tid < B_ && tid < out_size) out[tid] = (float)g_action[tid];
    if (tid == 0 && out_size > B_) out[B_] = loss;
    for (int i = B_ + 1 + tid; i < out_size; i += 256) out[i] = 0.0f;
}

// ---------------- launch -----------------------------------------------------
extern "C" void kernel_launch(void* const* d_in, const int* in_sizes, int n_in,
                              void* d_out, int out_size) {
    const float* inputs = (const float*)d_in[0];
    const float* Wx     = (const float*)d_in[1];
    const float* Wh     = (const float*)d_in[2];
    const float* b_rnn  = (const float*)d_in[3];
    const float* W1     = (const float*)d_in[4];
    const float* b1     = (const float*)d_in[5];
    const float* W2     = (const float*)d_in[6];
    const float* b2     = (const float*)d_in[7];

    float *xw, *h, *hid, *logits;
    cudaGetSymbolAddress((void**)&xw,     g_xw);
    cudaGetSymbolAddress((void**)&h,      g_hbuf);
    cudaGetSymbolAddress((void**)&hid,    g_hid);
    cudaGetSymbolAddress((void**)&logits, g_logits);

    // xw = inputs @ Wx + b_rnn   (M=65536, N=1024, K=512)
    sgemm_kernel<128, 128, 16, 8, 8, 256, false>
        <<<dim3(H_ / 128, (B_ * T_) / 128), 256>>>(
            B_ * T_, H_, F_, inputs, F_, Wx, H_, b_rnn, xw, H_);

    // persistent recurrence + fused dense1
    const int smem = (int)sizeof(RecurSmem);  // 131072 + 16896
    cudaFuncSetAttribute(rnn_recur, cudaFuncAttributeMaxDynamicSharedMemorySize, smem);
    rnn_recur<<<NBLK, 256, smem>>>(xw, Wh, W1, b1, h, hid);

    // logits = hid @ W2 + b2   (N=1000, ragged)
    sgemm_kernel<32, 64, 16, 4, 4, 128, false>
        <<<dim3((A_ + 63) / 64, B_ / 32), 128>>>(
            B_, A_, H_, hid, H_, W2, A_, b2, logits, A_);

    sample_kernel<<<B_, 256>>>();
    finalize_kernel<<<1, 256>>>((float*)d_out, out_size);
}

// round 7
// speedup vs baseline: 1.5257x; 1.1326x over previous
#include <cuda_runtime.h>
#include <cstdint>

#define B_ 256
#define T_ 256
#define F_ 512
#define H_ 1024
#define A_ 1000

// recurrence: 128 blocks = 4 row-groups(64) x 8 col-groups(128) x 4 k-splits(256)
#define NBLK 128
#define RTHREADS 512
#define RROWS 64
#define RCOLS 128
#define RK    256
#define BKr   16
#define SPAD  66   // staging row pitch in u64

// ---------------- scratch (static device globals; no allocation) -------------
__device__ float g_xw[(size_t)B_ * T_ * H_];     // input projection [B][T][H]
__device__ float g_hbuf[B_ * H_];                // hidden state
__device__ float g_part[4][B_ * H_];             // k-split partials [q][m][n]
__device__ float g_hid[B_ * H_];
__device__ float g_logits[B_ * A_];
__device__ int   g_action[B_];
__device__ float g_rowloss[B_];

// grid barrier state (self-cleaning; safe across graph replays)
__device__ unsigned g_cnt = 0;
__device__ volatile unsigned g_gen = 0;

// ---------------- packed fp32x2 FMA helpers (Blackwell) ----------------------
__device__ __forceinline__ unsigned long long pack2(float lo, float hi) {
    unsigned long long r;
    asm("mov.b64 %0, {%1, %2};" : "=l"(r) : "f"(lo), "f"(hi));
    return r;
}
__device__ __forceinline__ void unpack2(unsigned long long v, float& lo, float& hi) {
    asm("mov.b64 {%0, %1}, %2;" : "=f"(lo), "=f"(hi) : "l"(v));
}
__device__ __forceinline__ void ffma2(unsigned long long& d, unsigned long long a,
                                      unsigned long long b) {
    asm("fma.rn.f32x2 %0, %1, %2, %0;" : "+l"(d) : "l"(a), "l"(b));
}

// ---------------- grid-wide barrier (no nanosleep — plain poll) --------------
__device__ __forceinline__ void grid_sync() {
    __syncthreads();
    if (threadIdx.x == 0) {
        __threadfence();
        unsigned gen = g_gen;
        unsigned old = atomicAdd(&g_cnt, 1u);
        if (old == NBLK - 1) {
            g_cnt = 0;
            __threadfence();
            g_gen = gen + 1;
        } else {
            while (g_gen == gen) { }
            __threadfence();
        }
    }
    __syncthreads();
}

// ---------------- persistent recurrence kernel -------------------------------
// Block (r,c,q): rows [r*64,+64), cols [c*128,+128), k in [q*256,+256).
// Slab Wh[k-range][col-range] (128 KB) resident in smem for all steps.
// 512 threads: ty=tid>>5 (4 rows), tx=tid&31 (4 cols). Per thread 4x4 outputs
// as 8 u64 fp32x2 pairs. Per inner-k: 2 broadcast LDS.128 (dup'd a) +
// 1 LDS.128 (b pairs) + 8 FFMA2.

struct RecurSmem {
    float Whs[RK * RCOLS];                       // 128 KB slab
    unsigned long long hsd[2 * BKr * SPAD];      // staging, dup'd (a,a) pairs
};

__device__ __forceinline__ void tile_gemm_part(
    const float* __restrict__ hrow,              // &h[(bm+m_l)*H + bk + kq]
    const float* __restrict__ Whs,
    unsigned long long* __restrict__ hsd,
    int ty, int tx, int m_l, int kq,
    unsigned long long acc[4][2])
{
    // stage chunk 0 (each thread: one float2 of h, duplicated into 2 u64)
    float2 pre = __ldcg((const float2*)hrow);
    {
        unsigned long long* d = &hsd[(0 * BKr + kq) * SPAD + m_l];
        d[0 * SPAD] = pack2(pre.x, pre.x);
        d[1 * SPAD] = pack2(pre.y, pre.y);
    }
    __syncthreads();

    const int nCh = RK / BKr;  // 16
    for (int kt = 0; kt < nCh; ++kt) {
        const int buf = kt & 1;
        if (kt + 1 < nCh)
            pre = __ldcg((const float2*)(hrow + (kt + 1) * BKr));

        const unsigned long long* as = &hsd[(buf * BKr) * SPAD + ty * 4];
        const float* ws = &Whs[tx * 4];
#pragma unroll
        for (int kk = 0; kk < BKr; ++kk) {
            ulonglong2 a01 = *(const ulonglong2*)(as + kk * SPAD);      // rows 0,1 (bcast)
            ulonglong2 a23 = *(const ulonglong2*)(as + kk * SPAD + 2);  // rows 2,3 (bcast)
            ulonglong2 b01 = *(const ulonglong2*)(ws + (kt * BKr + kk) * RCOLS);
            ffma2(acc[0][0], a01.x, b01.x); ffma2(acc[0][1], a01.x, b01.y);
            ffma2(acc[1][0], a01.y, b01.x); ffma2(acc[1][1], a01.y, b01.y);
            ffma2(acc[2][0], a23.x, b01.x); ffma2(acc[2][1], a23.x, b01.y);
            ffma2(acc[3][0], a23.y, b01.x); ffma2(acc[3][1], a23.y, b01.y);
        }

        if (kt + 1 < nCh) {
            unsigned long long* d = &hsd[(((buf ^ 1) * BKr) + kq) * SPAD + m_l];
            d[0 * SPAD] = pack2(pre.x, pre.x);
            d[1 * SPAD] = pack2(pre.y, pre.y);
        }
        __syncthreads();
    }
}

__device__ __forceinline__ void store_partials(
    unsigned long long acc[4][2], float* __restrict__ pq,
    int bm, int bn, int ty, int tx)
{
#pragma unroll
    for (int i = 0; i < 4; ++i) {
        const int m = bm + ty * 4 + i;
        float v0, v1, v2, v3;
        unpack2(acc[i][0], v0, v1);
        unpack2(acc[i][1], v2, v3);
        __stcg((float4*)&pq[(long)m * H_ + bn + tx * 4],
               make_float4(v0, v1, v2, v3));
    }
}

__global__ void __launch_bounds__(RTHREADS, 1)
rnn_recur(const float* __restrict__ xw, const float* __restrict__ Wh,
          const float* __restrict__ W1, const float* __restrict__ b1,
          float* __restrict__ h, float* __restrict__ hid)
{
    extern __shared__ __align__(16) char smraw[];
    RecurSmem* sm = (RecurSmem*)smraw;

    const int tid = threadIdx.x;
    const int bid = blockIdx.x;
    const int q = bid & 3;
    const int c = (bid >> 2) & 7;
    const int r = bid >> 5;
    const int bm = r * RROWS, bn = c * RCOLS, bk = q * RK;
    const int tx = tid & 31;        // cols bn + tx*4 .. +3
    const int ty = tid >> 5;        // rows bm + ty*4 .. +3
    const int m_l = tid >> 3;       // staging row 0..63
    const int kq  = (tid & 7) * 2;  // staging k offset {0,2,..,14}
    const int gtid = bid * RTHREADS + tid;     // 0..65535

    // load Wh slab [bk..bk+256) x [bn..bn+128) into smem (resident all steps)
    for (int v = tid; v < RK * RCOLS / 4; v += RTHREADS) {
        int k = v >> 5, nq = v & 31;
        float4 w = __ldg((const float4*)&Wh[(long)(bk + k) * H_ + bn + nq * 4]);
        *(float4*)&sm->Whs[k * RCOLS + nq * 4] = w;
    }

    // h_1 = relu(xw[:,0,:])  (h_0 == 0) — 65536 threads, one float4 each
    {
        int m = gtid >> 8, n4 = (gtid & 255) * 4;
        float4 v = __ldg((const float4*)&xw[((long)m * T_ + 0) * H_ + n4]);
        v.x = fmaxf(v.x, 0.f); v.y = fmaxf(v.y, 0.f);
        v.z = fmaxf(v.z, 0.f); v.w = fmaxf(v.w, 0.f);
        __stcg((float4*)&h[(long)m * H_ + n4], v);
    }
    grid_sync();

    for (int t = 1; t < T_; ++t) {
        unsigned long long acc[4][2];
#pragma unroll
        for (int i = 0; i < 4; ++i) { acc[i][0] = 0ull; acc[i][1] = 0ull; }

        tile_gemm_part(&h[(long)(bm + m_l) * H_ + bk + kq], sm->Whs, sm->hsd,
                       ty, tx, m_l, kq, acc);
        store_partials(acc, g_part[q], bm, bn, ty, tx);
        grid_sync();

        // reduce: h = relu(xw[:,t,:] + sum_q partial_q)
        {
            int m = gtid >> 8, n4 = (gtid & 255) * 4;
            long off = (long)m * H_ + n4;
            float4 s = __ldg((const float4*)&xw[((long)m * T_ + t) * H_ + n4]);
            float4 p0 = __ldcg((const float4*)&g_part[0][off]);
            float4 p1 = __ldcg((const float4*)&g_part[1][off]);
            float4 p2 = __ldcg((const float4*)&g_part[2][off]);
            float4 p3 = __ldcg((const float4*)&g_part[3][off]);
            s.x = fmaxf(s.x + p0.x + p1.x + p2.x + p3.x, 0.f);
            s.y = fmaxf(s.y + p0.y + p1.y + p2.y + p3.y, 0.f);
            s.z = fmaxf(s.z + p0.z + p1.z + p2.z + p3.z, 0.f);
            s.w = fmaxf(s.w + p0.w + p1.w + p2.w + p3.w, 0.f);
            __stcg((float4*)&h[off], s);
        }
        grid_sync();
    }
    // h now holds h_last (h_256)

    // fused dense1: hid = relu(h_last @ W1 + b1) — swap slab to W1
    for (int v = tid; v < RK * RCOLS / 4; v += RTHREADS) {
        int k = v >> 5, nq = v & 31;
        float4 w = __ldg((const float4*)&W1[(long)(bk + k) * H_ + bn + nq * 4]);
        *(float4*)&sm->Whs[k * RCOLS + nq * 4] = w;
    }
    __syncthreads();
    {
        unsigned long long acc[4][2];
#pragma unroll
        for (int i = 0; i < 4; ++i) { acc[i][0] = 0ull; acc[i][1] = 0ull; }
        tile_gemm_part(&h[(long)(bm + m_l) * H_ + bk + kq], sm->Whs, sm->hsd,
                       ty, tx, m_l, kq, acc);
        store_partials(acc, g_part[q], bm, bn, ty, tx);
        grid_sync();
        {
            int m = gtid >> 8, n4 = (gtid & 255) * 4;
            long off = (long)m * H_ + n4;
            float4 s = __ldg((const float4*)&b1[n4]);
            float4 p0 = __ldcg((const float4*)&g_part[0][off]);
            float4 p1 = __ldcg((const float4*)&g_part[1][off]);
            float4 p2 = __ldcg((const float4*)&g_part[2][off]);
            float4 p3 = __ldcg((const float4*)&g_part[3][off]);
            s.x = fmaxf(s.x + p0.x + p1.x + p2.x + p3.x, 0.f);
            s.y = fmaxf(s.y + p0.y + p1.y + p2.y + p3.y, 0.f);
            s.z = fmaxf(s.z + p0.z + p1.z + p2.z + p3.z, 0.f);
            s.w = fmaxf(s.w + p0.w + p1.w + p2.w + p3.w, 0.f);
            __stcg((float4*)&hid[off], s);
        }
    }
}

// ---------------- double-buffered SGEMM template (dup-A) ---------------------
template <int BM, int BN, int BK, int TM, int TN, int THREADS, bool RELU>
__global__ void __launch_bounds__(THREADS)
sgemm_kernel(int M, int N, int K,
             const float* __restrict__ A, int lda,
             const float* __restrict__ Bm, int ldb,
             const float* __restrict__ bias,
             float* __restrict__ C, int ldc)
{
    static_assert(TN % 4 == 0 && TM % 2 == 0, "");
    constexpr int TX = BN / TN;
    constexpr int TY = BM / TM;
    static_assert(TX * TY == THREADS, "");

    __shared__ __align__(16) unsigned long long As[2][BK][BM];
    __shared__ __align__(16) float Bs[2][BK][BN];

    const int tid = threadIdx.x;
    const int tx  = tid % TX;
    const int ty  = tid / TX;
    const int bm  = blockIdx.y * BM;
    const int bn  = blockIdx.x * BN;

    constexpr int A_VECS = BM * BK / 4;
    constexpr int A_PER  = A_VECS / THREADS;
    constexpr int B_VECS = BK * BN / 4;
    constexpr int B_PER  = B_VECS / THREADS;
    static_assert(A_VECS % THREADS == 0 && B_VECS % THREADS == 0, "");

    float4 aReg[A_PER];
    float4 bReg[B_PER];

    auto loadA = [&](int k0) {
#pragma unroll
        for (int i = 0; i < A_PER; ++i) {
            int v   = tid + i * THREADS;
            int row = v / (BK / 4);
            int kc  = (v % (BK / 4)) * 4;
            aReg[i] = *reinterpret_cast<const float4*>(
                &A[(long)(bm + row) * lda + k0 + kc]);
        }
    };
    auto loadB = [&](int k0) {
#pragma unroll
        for (int i = 0; i < B_PER; ++i) {
            int v    = tid + i * THREADS;
            int krow = v / (BN / 4);
            int nc   = (v % (BN / 4)) * 4;
            int col  = bn + nc;
            if (col < N)
                bReg[i] = *reinterpret_cast<const float4*>(
                    &Bm[(long)(k0 + krow) * ldb + col]);
            else
                bReg[i] = make_float4(0.f, 0.f, 0.f, 0.f);
        }
    };
    auto storeA = [&](int buf) {
#pragma unroll
        for (int i = 0; i < A_PER; ++i) {
            int v   = tid + i * THREADS;
            int row = v / (BK / 4);
            int kc  = (v % (BK / 4)) * 4;
            As[buf][kc + 0][row] = pack2(aReg[i].x, aReg[i].x);
            As[buf][kc + 1][row] = pack2(aReg[i].y, aReg[i].y);
            As[buf][kc + 2][row] = pack2(aReg[i].z, aReg[i].z);
            As[buf][kc + 3][row] = pack2(aReg[i].w, aReg[i].w);
        }
    };
    auto storeB = [&](int buf) {
#pragma unroll
        for (int i = 0; i < B_PER; ++i) {
            int v    = tid + i * THREADS;
            int krow = v / (BN / 4);
            int nc   = (v % (BN / 4)) * 4;
            *reinterpret_cast<float4*>(&Bs[buf][krow][nc]) = bReg[i];
        }
    };

    unsigned long long acc[TM][TN / 2];
#pragma unroll
    for (int i = 0; i < TM; ++i)
#pragma unroll
        for (int j = 0; j < TN / 2; ++j) acc[i][j] = 0ull;

    loadA(0); loadB(0);
    storeA(0); storeB(0);
    __syncthreads();

    const int nTiles = K / BK;
    for (int kt = 0; kt < nTiles; ++kt) {
        const int cur = kt & 1, nxt = cur ^ 1;
        if (kt + 1 < nTiles) { loadA((kt + 1) * BK); loadB((kt + 1) * BK); }

#pragma unroll
        for (int kk = 0; kk < BK; ++kk) {
            unsigned long long a2[TM];
#pragma unroll
            for (int i = 0; i < TM; i += 2) {
                ulonglong2 t = *reinterpret_cast<const ulonglong2*>(
                    &As[cur][kk][ty * TM + i]);
                a2[i] = t.x; a2[i + 1] = t.y;
            }
            unsigned long long b2[TN / 2];
#pragma unroll
            for (int j = 0; j < TN / 4; ++j) {
                ulonglong2 bv = *reinterpret_cast<const ulonglong2*>(
                    &Bs[cur][kk][tx * TN + 4 * j]);
                b2[2 * j] = bv.x; b2[2 * j + 1] = bv.y;
            }
#pragma unroll
            for (int i = 0; i < TM; ++i)
#pragma unroll
                for (int j = 0; j < TN / 2; ++j) ffma2(acc[i][j], a2[i], b2[j]);
        }

        if (kt + 1 < nTiles) { storeA(nxt); storeB(nxt); }
        __syncthreads();
    }

#pragma unroll
    for (int i = 0; i < TM; ++i) {
        const int m = bm + ty * TM + i;
#pragma unroll
        for (int j = 0; j < TN / 2; ++j) {
            float lo, hi;
            unpack2(acc[i][j], lo, hi);
            float v[2] = {lo, hi};
            const int n0 = bn + tx * TN + 2 * j;
#pragma unroll
            for (int e = 0; e < 2; ++e) {
                const int n = n0 + e;
                if (n < N) {
                    float cv = v[e];
                    if (bias) cv += bias[n];
                    if (RELU) cv = fmaxf(cv, 0.0f);
                    C[(long)m * ldc + n] = cv;
                }
            }
        }
    }
}

// ---------------- threefry2x32 / JAX gumbel ----------------------------------
__device__ __forceinline__ float gumbel_at(uint32_t idx) {
    const uint32_t k0 = 0u, k1 = 42u;
    const uint32_t ks2 = k0 ^ k1 ^ 0x1BD11BDAu;
    uint32_t x0 = k0;
    uint32_t x1 = idx + k1;
#define RND(r) { x0 += x1; x1 = ((x1 << (r)) | (x1 >> (32 - (r)))) ^ x0; }
    RND(13) RND(15) RND(26) RND(6)   x0 += k1;  x1 += ks2 + 1u;
    RND(17) RND(29) RND(16) RND(24)  x0 += ks2; x1 += k0 + 2u;
    RND(13) RND(15) RND(26) RND(6)   x0 += k0;  x1 += k1 + 3u;
    RND(17) RND(29) RND(16) RND(24)  x0 += k1;  x1 += ks2 + 4u;
    RND(13) RND(15) RND(26) RND(6)   x0 += ks2; x1 += k0 + 5u;
#undef RND
    const uint32_t bits = x0 ^ x1;
    float f = __uint_as_float((bits >> 9) | 0x3f800000u) - 1.0f;
    float u = fmaxf(f, 1.17549435e-38f);
    return -logf(-logf(u));
}

// ---------------- softmax+sample, finalize -----------------------------------
__global__ void sample_kernel() {
    const int b = blockIdx.x;
    const float* __restrict__ row = g_logits + (long)b * A_;
    const int tid = threadIdx.x;
    __shared__ float sred[256];
    __shared__ int   sidx[256];

    float mx = -3.402823466e38f;
    for (int a = tid; a < A_; a += 256) mx = fmaxf(mx, row[a]);
    sred[tid] = mx; __syncthreads();
    for (int s = 128; s; s >>= 1) {
        if (tid < s) sred[tid] = fmaxf(sred[tid], sred[tid + s]);
        __syncthreads();
    }
    const float rmax = sred[0]; __syncthreads();

    float sum = 0.f;
    for (int a = tid; a < A_; a += 256) sum += expf(row[a] - rmax);
    sred[tid] = sum; __syncthreads();
    for (int s = 128; s; s >>= 1) {
        if (tid < s) sred[tid] += sred[tid + s];
        __syncthreads();
    }
    const float rsum = sred[0]; __syncthreads();

    float bestv = -3.402823466e38f;
    int   besti = A_;
    for (int a = tid; a < A_; a += 256) {
        float p = expf(row[a] - rmax) / rsum;
        float v = p + gumbel_at((uint32_t)(b * A_ + a));
        if (v > bestv) { bestv = v; besti = a; }
    }
    sred[tid] = bestv; sidx[tid] = besti; __syncthreads();
    for (int s = 128; s; s >>= 1) {
        if (tid < s) {
            float v2 = sred[tid + s]; int i2 = sidx[tid + s];
            if (v2 > sred[tid] || (v2 == sred[tid] && i2 < sidx[tid])) {
                sred[tid] = v2; sidx[tid] = i2;
            }
        }
        __syncthreads();
    }
    if (tid == 0) {
        const int a = sidx[0];
        g_action[b] = a;
        float p = expf(row[a] - rmax) / rsum;
        p = fminf(fmaxf(p, 1e-7f), 1.0f - 1e-7f);
        g_rowloss[b] = -logf(p);
    }
}

__global__ void finalize_kernel(float* __restrict__ out, int out_size) {
    const int tid = threadIdx.x;
    __shared__ float red[256];
    red[tid] = g_rowloss[tid];
    __syncthreads();
    for (int s = 128; s; s >>= 1) {
        if (tid < s) red[tid] += red[tid + s];
        __syncthreads();
    }
    const float loss = red[0] / (float)B_;

    if (out_size == 1) {
        if (tid == 0) out[0] = loss;
        return;
    }
    if (tid < B_ && tid < out_size) out[tid] = (float)g_action[tid];
    if (tid == 0 && out_size > B_) out[B_] = loss;
    for (int i = B_ + 1 + tid; i < out_size; i += 256) out[i] = 0.0f;
}

// ---------------- launch -----------------------------------------------------
extern "C" void kernel_launch(void* const* d_in, const int* in_sizes, int n_in,
                              void* d_out, int out_size) {
    const float* inputs = (const float*)d_in[0];
    const float* Wx     = (const float*)d_in[1];
    const float* Wh     = (const float*)d_in[2];
    const float* b_rnn  = (const float*)d_in[3];
    const float* W1     = (const float*)d_in[4];
    const float* b1     = (const float*)d_in[5];
    const float* W2     = (const float*)d_in[6];
    const float* b2     = (const float*)d_in[7];

    float *xw, *h, *hid, *logits;
    cudaGetSymbolAddress((void**)&xw,     g_xw);
    cudaGetSymbolAddress((void**)&h,      g_hbuf);
    cudaGetSymbolAddress((void**)&hid,    g_hid);
    cudaGetSymbolAddress((void**)&logits, g_logits);

    // xw = inputs @ Wx + b_rnn   (M=65536, N=1024, K=512)
    sgemm_kernel<128, 64, 16, 8, 4, 256, false>
        <<<dim3(H_ / 64, (B_ * T_) / 128), 256>>>(
            B_ * T_, H_, F_, inputs, F_, Wx, H_, b_rnn, xw, H_);

    // persistent recurrence + fused dense1
    const int smem = (int)sizeof(RecurSmem);
    cudaFuncSetAttribute(rnn_recur, cudaFuncAttributeMaxDynamicSharedMemorySize, smem);
    rnn_recur<<<NBLK, RTHREADS, smem>>>(xw, Wh, W1, b1, h, hid);

    // logits = hid @ W2 + b2   (N=1000, ragged)
    sgemm_kernel<32, 64, 16, 4, 4, 128, false>
        <<<dim3((A_ + 63) / 64, B_ / 32), 128>>>(
            B_, A_, H_, hid, H_, W2, A_, b2, logits, A_);

    sample_kernel<<<B_, 256>>>();
    finalize_kernel<<<1, 256>>>((float*)d_out, out_size);
}

// round 8
// speedup vs baseline: 1.7629x; 1.1555x over previous
#include <cuda_runtime.h>
#include <cstdint>

#define B_ 256
#define T_ 256
#define F_ 512
#define H_ 1024
#define A_ 1000

// recurrence: 128 blocks = 2 row-groups(128) x 8 col-groups(128) x 8 k-splits(128)
#define NBLK 128
#define RTHREADS 512
#define RROWS 128
#define RCOLS 128
#define RK    128
#define NSPLIT 8
#define BKr   64
#define SPAD  130   // staging pitch in u64 per k-row (128 + 2 pad)

// ---------------- scratch (static device globals; no allocation) -------------
__device__ float g_xw[(size_t)B_ * T_ * H_];     // input projection [B][T][H]
__device__ float g_hbuf[B_ * H_];                // hidden state
__device__ float g_part[NSPLIT][B_ * H_];        // k-split partials [q][m][n]
__device__ float g_hid[B_ * H_];
__device__ float g_logits[B_ * A_];
__device__ int   g_action[B_];
__device__ float g_rowloss[B_];

// grid barrier state (self-cleaning; safe across graph replays)
__device__ unsigned g_cnt = 0;
__device__ volatile unsigned g_gen = 0;

// ---------------- packed fp32x2 FMA helpers (Blackwell) ----------------------
__device__ __forceinline__ unsigned long long pack2(float lo, float hi) {
    unsigned long long r;
    asm("mov.b64 %0, {%1, %2};" : "=l"(r) : "f"(lo), "f"(hi));
    return r;
}
__device__ __forceinline__ void unpack2(unsigned long long v, float& lo, float& hi) {
    asm("mov.b64 {%0, %1}, %2;" : "=f"(lo), "=f"(hi) : "l"(v));
}
__device__ __forceinline__ void ffma2(unsigned long long& d, unsigned long long a,
                                      unsigned long long b) {
    asm("fma.rn.f32x2 %0, %1, %2, %0;" : "+l"(d) : "l"(a), "l"(b));
}

// ---------------- grid-wide barrier ------------------------------------------
__device__ __forceinline__ void grid_sync() {
    __syncthreads();
    if (threadIdx.x == 0) {
        __threadfence();
        unsigned gen = g_gen;
        unsigned old = atomicAdd(&g_cnt, 1u);
        if (old == NBLK - 1) {
            g_cnt = 0;
            __threadfence();
            g_gen = gen + 1;
        } else {
            while (g_gen == gen) { }
            __threadfence();
        }
    }
    __syncthreads();
}

// ---------------- persistent recurrence kernel -------------------------------
// Block (r,c,q): rows [r*128,+128), cols [c*128,+128), k in [q*128,+128).
// Slab W[k-range][col-range] (64 KB) resident in smem for all steps.
// Staging: dup'd (a,a) u64 pairs, [2 chunks][64 k][SPAD rows].
// 512 threads: ty = tid>>5 = warp id (rows ty*8..+7, A-loads warp-broadcast),
// tx = tid&31 (cols tx*4..+3). Per thread 8x4 outputs = 16 u64 accs.
// Per inner-k per warp: 4x LDS.128 bcast (A) + 1x LDS.128 (B) + 16 FFMA2.
// bytes/MAC = 0.56 -> crossbar ~9.2K cyc/step vs FFMA2 floor 16.4K.

struct RecurSmem {
    float Whs[RK * RCOLS];                       // 64 KB slab
    unsigned long long hsd[2 * BKr * SPAD];      // 133 KB staging
};

__device__ __forceinline__ void stage_store(
    unsigned long long* __restrict__ hsd, int bufk0, int ko, int m_l,
    const float4 v[4])
{
#pragma unroll
    for (int j = 0; j < 4; ++j) {
        const int kl = bufk0 + ko + 16 * j;
        unsigned long long* d = &hsd[(size_t)kl * SPAD + m_l];
        d[0 * SPAD] = pack2(v[j].x, v[j].x);
        d[1 * SPAD] = pack2(v[j].y, v[j].y);
        d[2 * SPAD] = pack2(v[j].z, v[j].z);
        d[3 * SPAD] = pack2(v[j].w, v[j].w);
    }
}

__device__ __forceinline__ void compute_chunk(
    const unsigned long long* __restrict__ asb,   // &hsd[buf*64*SPAD + ty*8]
    const float* __restrict__ ws,                 // &Whs[buf*64*RCOLS + tx*4]
    unsigned long long acc[8][2])
{
#pragma unroll 16
    for (int kk = 0; kk < BKr; ++kk) {
        const unsigned long long* ar = asb + (size_t)kk * SPAD;
        ulonglong2 a01 = *(const ulonglong2*)(ar);
        ulonglong2 a23 = *(const ulonglong2*)(ar + 2);
        ulonglong2 a45 = *(const ulonglong2*)(ar + 4);
        ulonglong2 a67 = *(const ulonglong2*)(ar + 6);
        ulonglong2 b   = *(const ulonglong2*)(ws + (size_t)kk * RCOLS);
        ffma2(acc[0][0], a01.x, b.x); ffma2(acc[0][1], a01.x, b.y);
        ffma2(acc[1][0], a01.y, b.x); ffma2(acc[1][1], a01.y, b.y);
        ffma2(acc[2][0], a23.x, b.x); ffma2(acc[2][1], a23.x, b.y);
        ffma2(acc[3][0], a23.y, b.x); ffma2(acc[3][1], a23.y, b.y);
        ffma2(acc[4][0], a45.x, b.x); ffma2(acc[4][1], a45.x, b.y);
        ffma2(acc[5][0], a45.y, b.x); ffma2(acc[5][1], a45.y, b.y);
        ffma2(acc[6][0], a67.x, b.x); ffma2(acc[6][1], a67.x, b.y);
        ffma2(acc[7][0], a67.y, b.x); ffma2(acc[7][1], a67.y, b.y);
    }
}

// full 128x128x128 tile GEMM against the resident slab (2 chunks, dbl-buffered)
__device__ __forceinline__ void tile_gemm_part(
    const float* __restrict__ hrow,               // &h[(bm+m_l)*H_ + bk]
    const float* __restrict__ Whs,
    unsigned long long* __restrict__ hsd,
    int ty, int tx, int m_l, int ko,
    unsigned long long acc[8][2])
{
    float4 v[4];
#pragma unroll
    for (int j = 0; j < 4; ++j)
        v[j] = __ldcg((const float4*)(hrow + ko + 16 * j));
    stage_store(hsd, 0, ko, m_l, v);
    __syncthreads();

    // prefetch chunk 1 while computing chunk 0
#pragma unroll
    for (int j = 0; j < 4; ++j)
        v[j] = __ldcg((const float4*)(hrow + BKr + ko + 16 * j));

    compute_chunk(&hsd[ty * 8], &Whs[tx * 4], acc);

    stage_store(hsd, BKr, ko, m_l, v);
    __syncthreads();

    compute_chunk(&hsd[(size_t)BKr * SPAD + ty * 8],
                  &Whs[(size_t)BKr * RCOLS + tx * 4], acc);
}

__device__ __forceinline__ void store_partials(
    unsigned long long acc[8][2], float* __restrict__ pq,
    int bm, int bn, int ty, int tx)
{
#pragma unroll
    for (int i = 0; i < 8; ++i) {
        const int m = bm + ty * 8 + i;
        float v0, v1, v2, v3;
        unpack2(acc[i][0], v0, v1);
        unpack2(acc[i][1], v2, v3);
        __stcg((float4*)&pq[(long)m * H_ + bn + tx * 4],
               make_float4(v0, v1, v2, v3));
    }
}

__global__ void __launch_bounds__(RTHREADS, 1)
rnn_recur(const float* __restrict__ xw, const float* __restrict__ Wh,
          const float* __restrict__ W1, const float* __restrict__ b1,
          float* __restrict__ h, float* __restrict__ hid)
{
    extern __shared__ __align__(16) char smraw[];
    RecurSmem* sm = (RecurSmem*)smraw;

    const int tid = threadIdx.x;
    const int bid = blockIdx.x;
    const int q = bid & 7;
    const int c = (bid >> 3) & 7;
    const int r = bid >> 6;
    const int bm = r * RROWS, bn = c * RCOLS, bk = q * RK;
    const int tx = tid & 31;        // cols bn + tx*4 .. +3
    const int ty = tid >> 5;        // rows bm + ty*8 .. +7 (warp id)
    const int m_l = tid >> 2;       // staging row 0..127
    const int ko  = (tid & 3) * 4;  // staging k base (loads at ko + 16j)
    const int gtid = bid * RTHREADS + tid;   // 0..65535

    // load Wh slab [bk..bk+128) x [bn..bn+128) into smem (resident all steps)
    for (int v = tid; v < RK * RCOLS / 4; v += RTHREADS) {
        int k = v >> 5, nq = v & 31;
        float4 w = __ldg((const float4*)&Wh[(long)(bk + k) * H_ + bn + nq * 4]);
        *(float4*)&sm->Whs[k * RCOLS + nq * 4] = w;
    }

    // h_1 = relu(xw[:,0,:])  (h_0 == 0) — 65536 threads, one float4 each
    {
        int m = gtid >> 8, n4 = (gtid & 255) * 4;
        float4 v = __ldg((const float4*)&xw[((long)m * T_ + 0) * H_ + n4]);
        v.x = fmaxf(v.x, 0.f); v.y = fmaxf(v.y, 0.f);
        v.z = fmaxf(v.z, 0.f); v.w = fmaxf(v.w, 0.f);
        __stcg((float4*)&h[(long)m * H_ + n4], v);
    }
    grid_sync();

    for (int t = 1; t < T_; ++t) {
        unsigned long long acc[8][2];
#pragma unroll
        for (int i = 0; i < 8; ++i) { acc[i][0] = 0ull; acc[i][1] = 0ull; }

        tile_gemm_part(&h[(long)(bm + m_l) * H_ + bk], sm->Whs, sm->hsd,
                       ty, tx, m_l, ko, acc);
        store_partials(acc, g_part[q], bm, bn, ty, tx);
        grid_sync();

        // reduce: h = relu(xw[:,t,:] + sum_q partial_q)
        {
            int m = gtid >> 8, n4 = (gtid & 255) * 4;
            long off = (long)m * H_ + n4;
            float4 s = __ldg((const float4*)&xw[((long)m * T_ + t) * H_ + n4]);
#pragma unroll
            for (int qq = 0; qq < NSPLIT; ++qq) {
                float4 p = __ldcg((const float4*)&g_part[qq][off]);
                s.x += p.x; s.y += p.y; s.z += p.z; s.w += p.w;
            }
            s.x = fmaxf(s.x, 0.f); s.y = fmaxf(s.y, 0.f);
            s.z = fmaxf(s.z, 0.f); s.w = fmaxf(s.w, 0.f);
            __stcg((float4*)&h[off], s);
        }
        grid_sync();
    }
    // h now holds h_last (h_256)

    // fused dense1: hid = relu(h_last @ W1 + b1) — swap slab to W1
    for (int v = tid; v < RK * RCOLS / 4; v += RTHREADS) {
        int k = v >> 5, nq = v & 31;
        float4 w = __ldg((const float4*)&W1[(long)(bk + k) * H_ + bn + nq * 4]);
        *(float4*)&sm->Whs[k * RCOLS + nq * 4] = w;
    }
    __syncthreads();
    {
        unsigned long long acc[8][2];
#pragma unroll
        for (int i = 0; i < 8; ++i) { acc[i][0] = 0ull; acc[i][1] = 0ull; }
        tile_gemm_part(&h[(long)(bm + m_l) * H_ + bk], sm->Whs, sm->hsd,
                       ty, tx, m_l, ko, acc);
        store_partials(acc, g_part[q], bm, bn, ty, tx);
        grid_sync();
        {
            int m = gtid >> 8, n4 = (gtid & 255) * 4;
            long off = (long)m * H_ + n4;
            float4 s = __ldg((const float4*)&b1[n4]);
#pragma unroll
            for (int qq = 0; qq < NSPLIT; ++qq) {
                float4 p = __ldcg((const float4*)&g_part[qq][off]);
                s.x += p.x; s.y += p.y; s.z += p.z; s.w += p.w;
            }
            s.x = fmaxf(s.x, 0.f); s.y = fmaxf(s.y, 0.f);
            s.z = fmaxf(s.z, 0.f); s.w = fmaxf(s.w, 0.f);
            __stcg((float4*)&hid[off], s);
        }
    }
}

// ---------------- double-buffered SGEMM template (dup-A) ---------------------
template <int BM, int BN, int BK, int TM, int TN, int THREADS, bool RELU>
__global__ void __launch_bounds__(THREADS)
sgemm_kernel(int M, int N, int K,
             const float* __restrict__ A, int lda,
             const float* __restrict__ Bm, int ldb,
             const float* __restrict__ bias,
             float* __restrict__ C, int ldc)
{
    static_assert(TN % 4 == 0 && TM % 2 == 0, "");
    constexpr int TX = BN / TN;
    constexpr int TY = BM / TM;
    static_assert(TX * TY == THREADS, "");

    __shared__ __align__(16) unsigned long long As[2][BK][BM];
    __shared__ __align__(16) float Bs[2][BK][BN];

    const int tid = threadIdx.x;
    const int tx  = tid % TX;
    const int ty  = tid / TX;
    const int bm  = blockIdx.y * BM;
    const int bn  = blockIdx.x * BN;

    constexpr int A_VECS = BM * BK / 4;
    constexpr int A_PER  = A_VECS / THREADS;
    constexpr int B_VECS = BK * BN / 4;
    constexpr int B_PER  = B_VECS / THREADS;
    static_assert(A_VECS % THREADS == 0 && B_VECS % THREADS == 0, "");

    float4 aReg[A_PER];
    float4 bReg[B_PER];

    auto loadA = [&](int k0) {
#pragma unroll
        for (int i = 0; i < A_PER; ++i) {
            int v   = tid + i * THREADS;
            int row = v / (BK / 4);
            int kc  = (v % (BK / 4)) * 4;
            aReg[i] = *reinterpret_cast<const float4*>(
                &A[(long)(bm + row) * lda + k0 + kc]);
        }
    };
    auto loadB = [&](int k0) {
#pragma unroll
        for (int i = 0; i < B_PER; ++i) {
            int v    = tid + i * THREADS;
            int krow = v / (BN / 4);
            int nc   = (v % (BN / 4)) * 4;
            int col  = bn + nc;
            if (col < N)
                bReg[i] = *reinterpret_cast<const float4*>(
                    &Bm[(long)(k0 + krow) * ldb + col]);
            else
                bReg[i] = make_float4(0.f, 0.f, 0.f, 0.f);
        }
    };
    auto storeA = [&](int buf) {
#pragma unroll
        for (int i = 0; i < A_PER; ++i) {
            int v   = tid + i * THREADS;
            int row = v / (BK / 4);
            int kc  = (v % (BK / 4)) * 4;
            As[buf][kc + 0][row] = pack2(aReg[i].x, aReg[i].x);
            As[buf][kc + 1][row] = pack2(aReg[i].y, aReg[i].y);
            As[buf][kc + 2][row] = pack2(aReg[i].z, aReg[i].z);
            As[buf][kc + 3][row] = pack2(aReg[i].w, aReg[i].w);
        }
    };
    auto storeB = [&](int buf) {
#pragma unroll
        for (int i = 0; i < B_PER; ++i) {
            int v    = tid + i * THREADS;
            int krow = v / (BN / 4);
            int nc   = (v % (BN / 4)) * 4;
            *reinterpret_cast<float4*>(&Bs[buf][krow][nc]) = bReg[i];
        }
    };

    unsigned long long acc[TM][TN / 2];
#pragma unroll
    for (int i = 0; i < TM; ++i)
#pragma unroll
        for (int j = 0; j < TN / 2; ++j) acc[i][j] = 0ull;

    loadA(0); loadB(0);
    storeA(0); storeB(0);
    __syncthreads();

    const int nTiles = K / BK;
    for (int kt = 0; kt < nTiles; ++kt) {
        const int cur = kt & 1, nxt = cur ^ 1;
        if (kt + 1 < nTiles) { loadA((kt + 1) * BK); loadB((kt + 1) * BK); }

#pragma unroll
        for (int kk = 0; kk < BK; ++kk) {
            unsigned long long a2[TM];
#pragma unroll
            for (int i = 0; i < TM; i += 2) {
                ulonglong2 t = *reinterpret_cast<const ulonglong2*>(
                    &As[cur][kk][ty * TM + i]);
                a2[i] = t.x; a2[i + 1] = t.y;
            }
            unsigned long long b2[TN / 2];
#pragma unroll
            for (int j = 0; j < TN / 4; ++j) {
                ulonglong2 bv = *reinterpret_cast<const ulonglong2*>(
                    &Bs[cur][kk][tx * TN + 4 * j]);
                b2[2 * j] = bv.x; b2[2 * j + 1] = bv.y;
            }
#pragma unroll
            for (int i = 0; i < TM; ++i)
#pragma unroll
                for (int j = 0; j < TN / 2; ++j) ffma2(acc[i][j], a2[i], b2[j]);
        }

        if (kt + 1 < nTiles) { storeA(nxt); storeB(nxt); }
        __syncthreads();
    }

#pragma unroll
    for (int i = 0; i < TM; ++i) {
        const int m = bm + ty * TM + i;
#pragma unroll
        for (int j = 0; j < TN / 2; ++j) {
            float lo, hi;
            unpack2(acc[i][j], lo, hi);
            float v[2] = {lo, hi};
            const int n0 = bn + tx * TN + 2 * j;
#pragma unroll
            for (int e = 0; e < 2; ++e) {
                const int n = n0 + e;
                if (n < N) {
                    float cv = v[e];
                    if (bias) cv += bias[n];
                    if (RELU) cv = fmaxf(cv, 0.0f);
                    C[(long)m * ldc + n] = cv;
                }
            }
        }
    }
}

// ---------------- threefry2x32 / JAX gumbel ----------------------------------
__device__ __forceinline__ float gumbel_at(uint32_t idx) {
    const uint32_t k0 = 0u, k1 = 42u;
    const uint32_t ks2 = k0 ^ k1 ^ 0x1BD11BDAu;
    uint32_t x0 = k0;
    uint32_t x1 = idx + k1;
#define RND(r) { x0 += x1; x1 = ((x1 << (r)) | (x1 >> (32 - (r)))) ^ x0; }
    RND(13) RND(15) RND(26) RND(6)   x0 += k1;  x1 += ks2 + 1u;
    RND(17) RND(29) RND(16) RND(24)  x0 += ks2; x1 += k0 + 2u;
    RND(13) RND(15) RND(26) RND(6)   x0 += k0;  x1 += k1 + 3u;
    RND(17) RND(29) RND(16) RND(24)  x0 += k1;  x1 += ks2 + 4u;
    RND(13) RND(15) RND(26) RND(6)   x0 += ks2; x1 += k0 + 5u;
#undef RND
    const uint32_t bits = x0 ^ x1;
    float f = __uint_as_float((bits >> 9) | 0x3f800000u) - 1.0f;
    float u = fmaxf(f, 1.17549435e-38f);
    return -logf(-logf(u));
}

// ---------------- softmax+sample, finalize -----------------------------------
__global__ void sample_kernel() {
    const int b = blockIdx.x;
    const float* __restrict__ row = g_logits + (long)b * A_;
    const int tid = threadIdx.x;
    __shared__ float sred[256];
    __shared__ int   sidx[256];

    float mx = -3.402823466e38f;
    for (int a = tid; a < A_; a += 256) mx = fmaxf(mx, row[a]);
    sred[tid] = mx; __syncthreads();
    for (int s = 128; s; s >>= 1) {
        if (tid < s) sred[tid] = fmaxf(sred[tid], sred[tid + s]);
        __syncthreads();
    }
    const float rmax = sred[0]; __syncthreads();

    float sum = 0.f;
    for (int a = tid; a < A_; a += 256) sum += expf(row[a] - rmax);
    sred[tid] = sum; __syncthreads();
    for (int s = 128; s; s >>= 1) {
        if (tid < s) sred[tid] += sred[tid + s];
        __syncthreads();
    }
    const float rsum = sred[0]; __syncthreads();

    float bestv = -3.402823466e38f;
    int   besti = A_;
    for (int a = tid; a < A_; a += 256) {
        float p = expf(row[a] - rmax) / rsum;
        float v = p + gumbel_at((uint32_t)(b * A_ + a));
        if (v > bestv) { bestv = v; besti = a; }
    }
    sred[tid] = bestv; sidx[tid] = besti; __syncthreads();
    for (int s = 128; s; s >>= 1) {
        if (tid < s) {
            float v2 = sred[tid + s]; int i2 = sidx[tid + s];
            if (v2 > sred[tid] || (v2 == sred[tid] && i2 < sidx[tid])) {
                sred[tid] = v2; sidx[tid] = i2;
            }
        }
        __syncthreads();
    }
    if (tid == 0) {
        const int a = sidx[0];
        g_action[b] = a;
        float p = expf(row[a] - rmax) / rsum;
        p = fminf(fmaxf(p, 1e-7f), 1.0f - 1e-7f);
        g_rowloss[b] = -logf(p);
    }
}

__global__ void finalize_kernel(float* __restrict__ out, int out_size) {
    const int tid = threadIdx.x;
    __shared__ float red[256];
    red[tid] = g_rowloss[tid];
    __syncthreads();
    for (int s = 128; s; s >>= 1) {
        if (tid < s) red[tid] += red[tid + s];
        __syncthreads();
    }
    const float loss = red[0] / (float)B_;

    if (out_size == 1) {
        if (tid == 0) out[0] = loss;
        return;
    }
    if (tid < B_ && tid < out_size) out[tid] = (float)g_action[tid];
    if (tid == 0 && out_size > B_) out[B_] = loss;
    for (int i = B_ + 1 + tid; i < out_size; i += 256) out[i] = 0.0f;
}

// ---------------- launch -----------------------------------------------------
extern "C" void kernel_launch(void* const* d_in, const int* in_sizes, int n_in,
                              void* d_out, int out_size) {
    const float* inputs = (const float*)d_in[0];
    const float* Wx     = (const float*)d_in[1];
    const float* Wh     = (const float*)d_in[2];
    const float* b_rnn  = (const float*)d_in[3];
    const float* W1     = (const float*)d_in[4];
    const float* b1     = (const float*)d_in[5];
    const float* W2     = (const float*)d_in[6];
    const float* b2     = (const float*)d_in[7];

    float *xw, *h, *hid, *logits;
    cudaGetSymbolAddress((void**)&xw,     g_xw);
    cudaGetSymbolAddress((void**)&h,      g_hbuf);
    cudaGetSymbolAddress((void**)&hid,    g_hid);
    cudaGetSymbolAddress((void**)&logits, g_logits);

    // xw = inputs @ Wx + b_rnn   (M=65536, N=1024, K=512)
    sgemm_kernel<128, 64, 16, 8, 4, 256, false>
        <<<dim3(H_ / 64, (B_ * T_) / 128), 256>>>(
            B_ * T_, H_, F_, inputs, F_, Wx, H_, b_rnn, xw, H_);

    // persistent recurrence + fused dense1
    const int smem = (int)sizeof(RecurSmem);  // 65536 + 133120 = 198656
    cudaFuncSetAttribute(rnn_recur, cudaFuncAttributeMaxDynamicSharedMemorySize, smem);
    rnn_recur<<<NBLK, RTHREADS, smem>>>(xw, Wh, W1, b1, h, hid);

    // logits = hid @ W2 + b2   (N=1000, ragged)
    sgemm_kernel<32, 64, 16, 4, 4, 128, false>
        <<<dim3((A_ + 63) / 64, B_ / 32), 128>>>(
            B_, A_, H_, hid, H_, W2, A_, b2, logits, A_);

    sample_kernel<<<B_, 256>>>();
    finalize_kernel<<<1, 256>>>((float*)d_out, out_size);
}